// round 1
// baseline (speedup 1.0000x reference)
#include <cuda_runtime.h>
#include <cstddef>

// Problem constants
#define BWT   1024          // number of windows (batch*windows)
#define WIN_  128           // window size
#define CH    512           // channels
#define NHH   8             // heads
#define HDD   64            // head dim
#define MROWS (BWT * WIN_)  // 131072 token rows
#define N1    (3 * CH)      // 1536
#define KC    CH            // 512

// ---------------- scratch (device globals; no allocations allowed) ----------
__device__ float g_qkv[(size_t)MROWS * N1];   // 805 MB: qkv = x @ w_qkv + b
__device__ float g_att[(size_t)MROWS * CH];   // 268 MB: attention output

// ---------------- packed f32x2 helpers (Blackwell FFMA2) --------------------
typedef unsigned long long u64t;

__device__ __forceinline__ u64t pack2(float x, float y) {
    u64t r;
    asm("mov.b64 %0, {%1, %2};" : "=l"(r) : "f"(x), "f"(y));
    return r;
}
__device__ __forceinline__ void fma2(u64t& d, u64t a, u64t b) {
    asm("fma.rn.f32x2 %0, %1, %2, %0;" : "+l"(d) : "l"(a), "l"(b));
}
__device__ __forceinline__ float2 unpack2(u64t v) {
    float2 r;
    asm("mov.b64 {%0, %1}, %2;" : "=f"(r.x), "=f"(r.y) : "l"(v));
    return r;
}

// ---------------- SGEMM with bias: C[M,N] = A[M,K] @ B[K,N] + bias[N] -------
// 128x128 block tile, BK=8, 256 threads, 8x8 microtile, FFMA2 packed pairs.
__global__ __launch_bounds__(256, 2)
void sgemm_bias(const float* __restrict__ A, const float* __restrict__ Bm,
                const float* __restrict__ bias, float* __restrict__ C,
                int M, int N, int K)
{
    __shared__ float As[8][128];
    __shared__ float Bs[8][128];

    const int tid = threadIdx.x;
    const int bx = blockIdx.x, by = blockIdx.y;
    const int ty = tid >> 4, tx = tid & 15;

    const float* Ab = A + (size_t)by * 128 * K;
    const float* Bb = Bm + (size_t)bx * 128;

    const int aRow = tid >> 1, aCol = (tid & 1) * 4;
    const int bRow = tid >> 5, bCol = (tid & 31) * 4;

    u64t acc2[8][4];
#pragma unroll
    for (int i = 0; i < 8; i++)
#pragma unroll
        for (int j = 0; j < 4; j++) acc2[i][j] = 0ULL;

    float4 a4 = *(const float4*)(Ab + (size_t)aRow * K + aCol);
    float4 b4 = *(const float4*)(Bb + (size_t)bRow * N + bCol);

    for (int k0 = 0; k0 < K; k0 += 8) {
        As[aCol + 0][aRow] = a4.x;
        As[aCol + 1][aRow] = a4.y;
        As[aCol + 2][aRow] = a4.z;
        As[aCol + 3][aRow] = a4.w;
        *(float4*)&Bs[bRow][bCol] = b4;
        __syncthreads();

        if (k0 + 8 < K) {
            a4 = *(const float4*)(Ab + (size_t)aRow * K + (k0 + 8) + aCol);
            b4 = *(const float4*)(Bb + (size_t)(k0 + 8 + bRow) * N + bCol);
        }

#pragma unroll
        for (int kk = 0; kk < 8; kk++) {
            float ar[8], br[8];
#pragma unroll
            for (int i = 0; i < 8; i++) ar[i] = As[kk][ty * 8 + i];
#pragma unroll
            for (int j = 0; j < 8; j++) br[j] = Bs[kk][tx * 8 + j];

            u64t a2[8], b2[4];
#pragma unroll
            for (int i = 0; i < 8; i++) a2[i] = pack2(ar[i], ar[i]);
#pragma unroll
            for (int j = 0; j < 4; j++) b2[j] = pack2(br[2 * j], br[2 * j + 1]);
#pragma unroll
            for (int i = 0; i < 8; i++)
#pragma unroll
                for (int j = 0; j < 4; j++) fma2(acc2[i][j], a2[i], b2[j]);
        }
        __syncthreads();
    }

#pragma unroll
    for (int i = 0; i < 8; i++) {
        size_t row = (size_t)by * 128 + ty * 8 + i;
        float* crow = C + row * N + (size_t)bx * 128 + tx * 8;
        const float* brow = bias + (size_t)bx * 128 + tx * 8;
#pragma unroll
        for (int j2 = 0; j2 < 2; j2++) {
            float2 p0 = unpack2(acc2[i][2 * j2 + 0]);
            float2 p1 = unpack2(acc2[i][2 * j2 + 1]);
            float4 o;
            o.x = p0.x + brow[4 * j2 + 0];
            o.y = p0.y + brow[4 * j2 + 1];
            o.z = p1.x + brow[4 * j2 + 2];
            o.w = p1.y + brow[4 * j2 + 3];
            *(float4*)(crow + 4 * j2) = o;
        }
    }
}

// ---------------- Window attention: one CTA per (head, window) --------------
// smem: Q[128][65], K[128][65], V[128][64], S[128][128], bias[255+pad]
#define QK_STRIDE 65
#define ATTN_SMEM_FLOATS (128 * QK_STRIDE * 2 + 128 * 64 + 128 * 128 + 256)
#define ATTN_SMEM_BYTES  (ATTN_SMEM_FLOATS * 4)

__global__ __launch_bounds__(256)
void attn_kernel(const float* __restrict__ qkv, const float* __restrict__ mask,
                 const float* __restrict__ btab, float* __restrict__ att)
{
    const int h   = blockIdx.x;   // 0..7
    const int b   = blockIdx.y;   // 0..1023
    const int tid = threadIdx.x;
    const int lane = tid & 31, warp = tid >> 5;
    const int ty = tid >> 4, tx = tid & 15;

    extern __shared__ float sm[];
    float* Qs = sm;                         // 128 x 65
    float* Ks = Qs + 128 * QK_STRIDE;       // 128 x 65
    float* Vs = Ks + 128 * QK_STRIDE;       // 128 x 64
    float* Ss = Vs + 128 * 64;              // 128 x 128
    float* bs = Ss + 128 * 128;             // 255 bias values for this head

    const size_t row0 = (size_t)b * WIN_;
    const float* qb = qkv + row0 * N1 + h * HDD;
    const float* kb = qb + CH;
    const float* vb = qb + 2 * CH;

    // Load Q, K (stride 65), V (stride 64). 128 rows x 64 cols each.
    for (int i = tid; i < 128 * 16; i += 256) {
        int r = i >> 4, c4 = (i & 15) << 2;
        float4 q4 = *(const float4*)(qb + (size_t)r * N1 + c4);
        float4 k4 = *(const float4*)(kb + (size_t)r * N1 + c4);
        float4 v4 = *(const float4*)(vb + (size_t)r * N1 + c4);
        float* qd = Qs + r * QK_STRIDE + c4;
        qd[0] = q4.x; qd[1] = q4.y; qd[2] = q4.z; qd[3] = q4.w;
        float* kd = Ks + r * QK_STRIDE + c4;
        kd[0] = k4.x; kd[1] = k4.y; kd[2] = k4.z; kd[3] = k4.w;
        *(float4*)(Vs + r * 64 + c4) = v4;
    }
    if (tid < 255) bs[tid] = btab[tid * NHH + h];
    __syncthreads();

    // ---- S = Q K^T : thread (ty,tx) -> q rows ty*8..+7, k cols {tx+16j} ----
    float acc[8][8];
#pragma unroll
    for (int i = 0; i < 8; i++)
#pragma unroll
        for (int j = 0; j < 8; j++) acc[i][j] = 0.0f;

#pragma unroll 4
    for (int d = 0; d < 64; d++) {
        float qv[8], kv[8];
#pragma unroll
        for (int i = 0; i < 8; i++) qv[i] = Qs[(ty * 8 + i) * QK_STRIDE + d];
#pragma unroll
        for (int j = 0; j < 8; j++) kv[j] = Ks[(tx + 16 * j) * QK_STRIDE + d];
#pragma unroll
        for (int i = 0; i < 8; i++)
#pragma unroll
            for (int j = 0; j < 8; j++)
                acc[i][j] = fmaf(qv[i], kv[j], acc[i][j]);
    }

    // scale + relative-position bias + window mask, write S
    const int wdw = b & 63;  // b % nW
    const float* mrow = mask + (size_t)wdw * (WIN_ * WIN_);
#pragma unroll
    for (int i = 0; i < 8; i++) {
        int q = ty * 8 + i;
#pragma unroll
        for (int j = 0; j < 8; j++) {
            int k = tx + 16 * j;
            Ss[q * 128 + k] = acc[i][j] * 0.125f + bs[k - q + 127] + mrow[q * 128 + k];
        }
    }
    __syncthreads();

    // ---- softmax over k: each warp handles 16 rows, 4 elems/lane ----
    for (int qq = 0; qq < 16; qq++) {
        int q = warp * 16 + qq;
        float4 x = *(float4*)(Ss + q * 128 + lane * 4);
        float m = fmaxf(fmaxf(x.x, x.y), fmaxf(x.z, x.w));
#pragma unroll
        for (int o = 16; o; o >>= 1) m = fmaxf(m, __shfl_xor_sync(0xffffffffu, m, o));
        float e0 = expf(x.x - m);
        float e1 = expf(x.y - m);
        float e2 = expf(x.z - m);
        float e3 = expf(x.w - m);
        float s = (e0 + e1) + (e2 + e3);
#pragma unroll
        for (int o = 16; o; o >>= 1) s += __shfl_xor_sync(0xffffffffu, s, o);
        float inv = 1.0f / s;
        *(float4*)(Ss + q * 128 + lane * 4) = make_float4(e0 * inv, e1 * inv, e2 * inv, e3 * inv);
    }
    __syncthreads();

    // ---- O = P V : thread (ty,tx) -> q rows ty*8..+7, d cols tx*4..+3 ----
    float o[8][4];
#pragma unroll
    for (int i = 0; i < 8; i++)
#pragma unroll
        for (int c = 0; c < 4; c++) o[i][c] = 0.0f;

#pragma unroll 2
    for (int k0 = 0; k0 < 128; k0 += 4) {
        float4 vv[4];
#pragma unroll
        for (int j = 0; j < 4; j++) vv[j] = *(const float4*)(Vs + (k0 + j) * 64 + tx * 4);
#pragma unroll
        for (int i = 0; i < 8; i++) {
            float4 p = *(const float4*)(Ss + (ty * 8 + i) * 128 + k0);
            o[i][0] = fmaf(p.x, vv[0].x, o[i][0]);
            o[i][1] = fmaf(p.x, vv[0].y, o[i][1]);
            o[i][2] = fmaf(p.x, vv[0].z, o[i][2]);
            o[i][3] = fmaf(p.x, vv[0].w, o[i][3]);
            o[i][0] = fmaf(p.y, vv[1].x, o[i][0]);
            o[i][1] = fmaf(p.y, vv[1].y, o[i][1]);
            o[i][2] = fmaf(p.y, vv[1].z, o[i][2]);
            o[i][3] = fmaf(p.y, vv[1].w, o[i][3]);
            o[i][0] = fmaf(p.z, vv[2].x, o[i][0]);
            o[i][1] = fmaf(p.z, vv[2].y, o[i][1]);
            o[i][2] = fmaf(p.z, vv[2].z, o[i][2]);
            o[i][3] = fmaf(p.z, vv[2].w, o[i][3]);
            o[i][0] = fmaf(p.w, vv[3].x, o[i][0]);
            o[i][1] = fmaf(p.w, vv[3].y, o[i][1]);
            o[i][2] = fmaf(p.w, vv[3].z, o[i][2]);
            o[i][3] = fmaf(p.w, vv[3].w, o[i][3]);
        }
    }

    float* ob = att + row0 * CH + h * HDD;
#pragma unroll
    for (int i = 0; i < 8; i++) {
        *(float4*)(ob + (size_t)(ty * 8 + i) * CH + tx * 4) =
            make_float4(o[i][0], o[i][1], o[i][2], o[i][3]);
    }
}

// ---------------- launch ----------------------------------------------------
extern "C" void kernel_launch(void* const* d_in, const int* in_sizes, int n_in,
                              void* d_out, int out_size)
{
    const float* x      = (const float*)d_in[0];
    const float* mask   = (const float*)d_in[1];
    const float* w_qkv  = (const float*)d_in[2];
    const float* b_qkv  = (const float*)d_in[3];
    const float* w_proj = (const float*)d_in[4];
    const float* b_proj = (const float*)d_in[5];
    const float* btab   = (const float*)d_in[6];
    float* out = (float*)d_out;

    float *qkv_s = nullptr, *att_s = nullptr;
    cudaGetSymbolAddress((void**)&qkv_s, g_qkv);
    cudaGetSymbolAddress((void**)&att_s, g_att);

    cudaFuncSetAttribute(attn_kernel, cudaFuncAttributeMaxDynamicSharedMemorySize,
                         ATTN_SMEM_BYTES);

    dim3 blk(256);
    // GEMM1: qkv = x @ w_qkv + b_qkv   (131072 x 1536)
    sgemm_bias<<<dim3(N1 / 128, MROWS / 128), blk>>>(x, w_qkv, b_qkv, qkv_s,
                                                     MROWS, N1, KC);
    // Attention per (head, window)
    attn_kernel<<<dim3(NHH, BWT), blk, ATTN_SMEM_BYTES>>>(qkv_s, mask, btab, att_s);
    // GEMM2: out = att @ w_proj + b_proj   (131072 x 512)
    sgemm_bias<<<dim3(CH / 128, MROWS / 128), blk>>>(att_s, w_proj, b_proj, out,
                                                     MROWS, CH, KC);
}

// round 2
// speedup vs baseline: 1.1216x; 1.1216x over previous
#include <cuda_runtime.h>
#include <cstddef>

// Problem constants
#define BWT   1024          // number of windows (batch*windows)
#define WIN_  128           // window size
#define CH    512           // channels
#define NHH   8             // heads
#define HDD   64            // head dim
#define MROWS (BWT * WIN_)  // 131072 token rows
#define N1    (3 * CH)      // 1536
#define KC    CH            // 512

// ---------------- scratch (device globals; no allocations allowed) ----------
__device__ float g_qkv[(size_t)MROWS * N1];   // 805 MB: qkv = x @ w_qkv + b
__device__ float g_att[(size_t)MROWS * CH];   // 268 MB: attention output

// ---------------- packed f32x2 helpers (Blackwell FFMA2) --------------------
typedef unsigned long long u64t;

__device__ __forceinline__ u64t pack2(float x, float y) {
    u64t r;
    asm("mov.b64 %0, {%1, %2};" : "=l"(r) : "f"(x), "f"(y));
    return r;
}
__device__ __forceinline__ void fma2(u64t& d, u64t a, u64t b) {
    asm("fma.rn.f32x2 %0, %1, %2, %0;" : "+l"(d) : "l"(a), "l"(b));
}
__device__ __forceinline__ float2 unpack2(u64t v) {
    float2 r;
    asm("mov.b64 {%0, %1}, %2;" : "=f"(r.x), "=f"(r.y) : "l"(v));
    return r;
}

// ---------------- SGEMM with bias: C[M,N] = A[M,K] @ B[K,N] + bias[N] -------
// 128x128 block tile, BK=8, 256 threads, 8x8 microtile, FFMA2 packed pairs.
// Thread (ty,tx): rows by*128 + ty*8..+7, cols bx*128 + {tx*4..+3, 64+tx*4..+3}.
// All smem reads are LDS.128, conflict-free (A broadcast, B contiguous).
__global__ __launch_bounds__(256, 2)
void sgemm_bias(const float* __restrict__ A, const float* __restrict__ Bm,
                const float* __restrict__ bias, float* __restrict__ C,
                int M, int N, int K)
{
    __shared__ float As[8][132];   // padded: transposed A store is conflict-free
    __shared__ float Bs[8][128];

    const int tid = threadIdx.x;
    const int bx = blockIdx.x, by = blockIdx.y;
    const int ty = tid >> 4, tx = tid & 15;

    const float* Ab = A + (size_t)by * 128 * K;
    const float* Bb = Bm + (size_t)bx * 128;

    const int aRow = tid >> 1, aCol = (tid & 1) * 4;
    const int bRow = tid >> 5, bCol = (tid & 31) * 4;

    // acc2[i][p]: row i, p=0,1 -> cols tx*4 + {0,1},{2,3}; p=2,3 -> 64+tx*4 + {0,1},{2,3}
    u64t acc2[8][4];
#pragma unroll
    for (int i = 0; i < 8; i++)
#pragma unroll
        for (int j = 0; j < 4; j++) acc2[i][j] = 0ULL;

    float4 a4 = *(const float4*)(Ab + (size_t)aRow * K + aCol);
    float4 b4 = *(const float4*)(Bb + (size_t)bRow * N + bCol);

    for (int k0 = 0; k0 < K; k0 += 8) {
        As[aCol + 0][aRow] = a4.x;
        As[aCol + 1][aRow] = a4.y;
        As[aCol + 2][aRow] = a4.z;
        As[aCol + 3][aRow] = a4.w;
        *(float4*)&Bs[bRow][bCol] = b4;
        __syncthreads();

        if (k0 + 8 < K) {
            a4 = *(const float4*)(Ab + (size_t)aRow * K + (k0 + 8) + aCol);
            b4 = *(const float4*)(Bb + (size_t)(k0 + 8 + bRow) * N + bCol);
        }

#pragma unroll
        for (int kk = 0; kk < 8; kk++) {
            float4 a0 = *(const float4*)&As[kk][ty * 8];
            float4 a1 = *(const float4*)&As[kk][ty * 8 + 4];
            float4 b0 = *(const float4*)&Bs[kk][tx * 4];
            float4 b1 = *(const float4*)&Bs[kk][64 + tx * 4];

            u64t bp[4];
            bp[0] = pack2(b0.x, b0.y);
            bp[1] = pack2(b0.z, b0.w);
            bp[2] = pack2(b1.x, b1.y);
            bp[3] = pack2(b1.z, b1.w);

            float ar[8] = {a0.x, a0.y, a0.z, a0.w, a1.x, a1.y, a1.z, a1.w};
#pragma unroll
            for (int i = 0; i < 8; i++) {
                u64t ai = pack2(ar[i], ar[i]);
#pragma unroll
                for (int j = 0; j < 4; j++) fma2(acc2[i][j], ai, bp[j]);
            }
        }
        __syncthreads();
    }

    // bias for this thread's two col groups
    const float4 bia0 = *(const float4*)(bias + (size_t)bx * 128 + tx * 4);
    const float4 bia1 = *(const float4*)(bias + (size_t)bx * 128 + 64 + tx * 4);

#pragma unroll
    for (int i = 0; i < 8; i++) {
        size_t row = (size_t)by * 128 + ty * 8 + i;
        float* crow = C + row * N + (size_t)bx * 128;

        float2 p0 = unpack2(acc2[i][0]);
        float2 p1 = unpack2(acc2[i][1]);
        float4 o0;
        o0.x = p0.x + bia0.x; o0.y = p0.y + bia0.y;
        o0.z = p1.x + bia0.z; o0.w = p1.y + bia0.w;
        *(float4*)(crow + tx * 4) = o0;

        float2 p2 = unpack2(acc2[i][2]);
        float2 p3 = unpack2(acc2[i][3]);
        float4 o1;
        o1.x = p2.x + bia1.x; o1.y = p2.y + bia1.y;
        o1.z = p3.x + bia1.z; o1.w = p3.y + bia1.w;
        *(float4*)(crow + 64 + tx * 4) = o1;
    }
}

// ---------------- Window attention: one CTA per (head, window) --------------
// smem: Q[128][65], K[128][65], V[128][64], S[128][128], bias[255+pad]
#define QK_STRIDE 65
#define ATTN_SMEM_FLOATS (128 * QK_STRIDE * 2 + 128 * 64 + 128 * 128 + 256)
#define ATTN_SMEM_BYTES  (ATTN_SMEM_FLOATS * 4)

__global__ __launch_bounds__(256)
void attn_kernel(const float* __restrict__ qkv, const float* __restrict__ mask,
                 const float* __restrict__ btab, float* __restrict__ att)
{
    const int h   = blockIdx.x;   // 0..7
    const int b   = blockIdx.y;   // 0..1023
    const int tid = threadIdx.x;
    const int lane = tid & 31, warp = tid >> 5;
    const int ty = tid >> 4, tx = tid & 15;

    extern __shared__ float sm[];
    float* Qs = sm;                         // 128 x 65
    float* Ks = Qs + 128 * QK_STRIDE;       // 128 x 65
    float* Vs = Ks + 128 * QK_STRIDE;       // 128 x 64
    float* Ss = Vs + 128 * 64;              // 128 x 128
    float* bs = Ss + 128 * 128;             // 255 bias values for this head

    const size_t row0 = (size_t)b * WIN_;
    const float* qb = qkv + row0 * N1 + h * HDD;
    const float* kb = qb + CH;
    const float* vb = qb + 2 * CH;

    // Load Q, K (stride 65), V (stride 64). 128 rows x 64 cols each.
    for (int i = tid; i < 128 * 16; i += 256) {
        int r = i >> 4, c4 = (i & 15) << 2;
        float4 q4 = *(const float4*)(qb + (size_t)r * N1 + c4);
        float4 k4 = *(const float4*)(kb + (size_t)r * N1 + c4);
        float4 v4 = *(const float4*)(vb + (size_t)r * N1 + c4);
        float* qd = Qs + r * QK_STRIDE + c4;
        qd[0] = q4.x; qd[1] = q4.y; qd[2] = q4.z; qd[3] = q4.w;
        float* kd = Ks + r * QK_STRIDE + c4;
        kd[0] = k4.x; kd[1] = k4.y; kd[2] = k4.z; kd[3] = k4.w;
        *(float4*)(Vs + r * 64 + c4) = v4;
    }
    if (tid < 255) bs[tid] = btab[tid * NHH + h];
    __syncthreads();

    // ---- S = Q K^T : thread (ty,tx) -> q rows ty*8..+7, k cols {tx+16j} ----
    float acc[8][8];
#pragma unroll
    for (int i = 0; i < 8; i++)
#pragma unroll
        for (int j = 0; j < 8; j++) acc[i][j] = 0.0f;

#pragma unroll 4
    for (int d = 0; d < 64; d++) {
        float qv[8], kv[8];
#pragma unroll
        for (int i = 0; i < 8; i++) qv[i] = Qs[(ty * 8 + i) * QK_STRIDE + d];
#pragma unroll
        for (int j = 0; j < 8; j++) kv[j] = Ks[(tx + 16 * j) * QK_STRIDE + d];
#pragma unroll
        for (int i = 0; i < 8; i++)
#pragma unroll
            for (int j = 0; j < 8; j++)
                acc[i][j] = fmaf(qv[i], kv[j], acc[i][j]);
    }

    // scale + relative-position bias + window mask, write S
    const int wdw = b & 63;  // b % nW
    const float* mrow = mask + (size_t)wdw * (WIN_ * WIN_);
#pragma unroll
    for (int i = 0; i < 8; i++) {
        int q = ty * 8 + i;
#pragma unroll
        for (int j = 0; j < 8; j++) {
            int k = tx + 16 * j;
            Ss[q * 128 + k] = acc[i][j] * 0.125f + bs[k - q + 127] + mrow[q * 128 + k];
        }
    }
    __syncthreads();

    // ---- softmax over k: each warp handles 16 rows, 4 elems/lane ----
    for (int qq = 0; qq < 16; qq++) {
        int q = warp * 16 + qq;
        float4 x = *(float4*)(Ss + q * 128 + lane * 4);
        float m = fmaxf(fmaxf(x.x, x.y), fmaxf(x.z, x.w));
#pragma unroll
        for (int o = 16; o; o >>= 1) m = fmaxf(m, __shfl_xor_sync(0xffffffffu, m, o));
        float e0 = expf(x.x - m);
        float e1 = expf(x.y - m);
        float e2 = expf(x.z - m);
        float e3 = expf(x.w - m);
        float s = (e0 + e1) + (e2 + e3);
#pragma unroll
        for (int o = 16; o; o >>= 1) s += __shfl_xor_sync(0xffffffffu, s, o);
        float inv = 1.0f / s;
        *(float4*)(Ss + q * 128 + lane * 4) = make_float4(e0 * inv, e1 * inv, e2 * inv, e3 * inv);
    }
    __syncthreads();

    // ---- O = P V : thread (ty,tx) -> q rows ty*8..+7, d cols tx*4..+3 ----
    float o[8][4];
#pragma unroll
    for (int i = 0; i < 8; i++)
#pragma unroll
        for (int c = 0; c < 4; c++) o[i][c] = 0.0f;

#pragma unroll 2
    for (int k0 = 0; k0 < 128; k0 += 4) {
        float4 vv[4];
#pragma unroll
        for (int j = 0; j < 4; j++) vv[j] = *(const float4*)(Vs + (k0 + j) * 64 + tx * 4);
#pragma unroll
        for (int i = 0; i < 8; i++) {
            float4 p = *(const float4*)(Ss + (ty * 8 + i) * 128 + k0);
            o[i][0] = fmaf(p.x, vv[0].x, o[i][0]);
            o[i][1] = fmaf(p.x, vv[0].y, o[i][1]);
            o[i][2] = fmaf(p.x, vv[0].z, o[i][2]);
            o[i][3] = fmaf(p.x, vv[0].w, o[i][3]);
            o[i][0] = fmaf(p.y, vv[1].x, o[i][0]);
            o[i][1] = fmaf(p.y, vv[1].y, o[i][1]);
            o[i][2] = fmaf(p.y, vv[1].z, o[i][2]);
            o[i][3] = fmaf(p.y, vv[1].w, o[i][3]);
            o[i][0] = fmaf(p.z, vv[2].x, o[i][0]);
            o[i][1] = fmaf(p.z, vv[2].y, o[i][1]);
            o[i][2] = fmaf(p.z, vv[2].z, o[i][2]);
            o[i][3] = fmaf(p.z, vv[2].w, o[i][3]);
            o[i][0] = fmaf(p.w, vv[3].x, o[i][0]);
            o[i][1] = fmaf(p.w, vv[3].y, o[i][1]);
            o[i][2] = fmaf(p.w, vv[3].z, o[i][2]);
            o[i][3] = fmaf(p.w, vv[3].w, o[i][3]);
        }
    }

    float* ob = att + row0 * CH + h * HDD;
#pragma unroll
    for (int i = 0; i < 8; i++) {
        *(float4*)(ob + (size_t)(ty * 8 + i) * CH + tx * 4) =
            make_float4(o[i][0], o[i][1], o[i][2], o[i][3]);
    }
}

// ---------------- launch ----------------------------------------------------
extern "C" void kernel_launch(void* const* d_in, const int* in_sizes, int n_in,
                              void* d_out, int out_size)
{
    const float* x      = (const float*)d_in[0];
    const float* mask   = (const float*)d_in[1];
    const float* w_qkv  = (const float*)d_in[2];
    const float* b_qkv  = (const float*)d_in[3];
    const float* w_proj = (const float*)d_in[4];
    const float* b_proj = (const float*)d_in[5];
    const float* btab   = (const float*)d_in[6];
    float* out = (float*)d_out;

    float *qkv_s = nullptr, *att_s = nullptr;
    cudaGetSymbolAddress((void**)&qkv_s, g_qkv);
    cudaGetSymbolAddress((void**)&att_s, g_att);

    cudaFuncSetAttribute(attn_kernel, cudaFuncAttributeMaxDynamicSharedMemorySize,
                         ATTN_SMEM_BYTES);

    dim3 blk(256);
    // GEMM1: qkv = x @ w_qkv + b_qkv   (131072 x 1536)
    sgemm_bias<<<dim3(N1 / 128, MROWS / 128), blk>>>(x, w_qkv, b_qkv, qkv_s,
                                                     MROWS, N1, KC);
    // Attention per (head, window)
    attn_kernel<<<dim3(NHH, BWT), blk, ATTN_SMEM_BYTES>>>(qkv_s, mask, btab, att_s);
    // GEMM2: out = att @ w_proj + b_proj   (131072 x 512)
    sgemm_bias<<<dim3(CH / 128, MROWS / 128), blk>>>(att_s, w_proj, b_proj, out,
                                                     MROWS, CH, KC);
}

// round 5
// speedup vs baseline: 1.3792x; 1.2297x over previous
#include <cuda_runtime.h>
#include <cuda_bf16.h>
#include <cstdint>
#include <cstddef>

// Problem constants
#define BWT   1024
#define WIN_  128
#define CH    512
#define NHH   8
#define HDD   64
#define MROWS (BWT * WIN_)   // 131072
#define N1    (3 * CH)       // 1536
#define KC    512

// ---------------- scratch (device globals) ----------------------------------
__device__ float         g_qkv[(size_t)MROWS * N1];   // fp32, feeds attention
__device__ __nv_bfloat16 g_xh[(size_t)MROWS * KC];
__device__ __nv_bfloat16 g_xl[(size_t)MROWS * KC];
__device__ __nv_bfloat16 g_ah[(size_t)MROWS * CH];    // attention out hi
__device__ __nv_bfloat16 g_al[(size_t)MROWS * CH];    // attention out lo
__device__ __nv_bfloat16 g_wqh[(size_t)N1 * KC];      // w_qkv^T  [N1][K]
__device__ __nv_bfloat16 g_wql[(size_t)N1 * KC];
__device__ __nv_bfloat16 g_wph[(size_t)CH * KC];      // w_proj^T [CH][K]
__device__ __nv_bfloat16 g_wpl[(size_t)CH * KC];

// ---------------- helpers ----------------------------------------------------
__device__ __forceinline__ uint32_t smem_u32(const void* p) {
    uint32_t a;
    asm("{ .reg .u64 t; cvta.to.shared.u64 t, %1; cvt.u32.u64 %0, t; }" : "=r"(a) : "l"(p));
    return a;
}
__device__ __forceinline__ void split_bf(float v, __nv_bfloat16& h, __nv_bfloat16& l) {
    h = __float2bfloat16_rn(v);
    l = __float2bfloat16_rn(v - __bfloat162float(h));
}

#define CP_ASYNC16(dst, src) \
    asm volatile("cp.async.cg.shared.global [%0], [%1], 16;" :: "r"(dst), "l"(src) : "memory")
#define CP_COMMIT()  asm volatile("cp.async.commit_group;" ::: "memory")
#define CP_WAIT1()   asm volatile("cp.async.wait_group 1;" ::: "memory")
#define CP_WAIT0()   asm volatile("cp.async.wait_group 0;" ::: "memory")

#define LDM4(r0, r1, r2, r3, addr) \
    asm volatile("ldmatrix.sync.aligned.m8n8.x4.shared.b16 {%0,%1,%2,%3}, [%4];" \
        : "=r"(r0), "=r"(r1), "=r"(r2), "=r"(r3) : "r"(addr))

#define MMA_BF16(d, a, b0, b1) \
    asm volatile("mma.sync.aligned.m16n8k16.row.col.f32.bf16.bf16.f32 " \
        "{%0,%1,%2,%3}, {%4,%5,%6,%7}, {%8,%9}, {%0,%1,%2,%3};" \
        : "+f"((d)[0]), "+f"((d)[1]), "+f"((d)[2]), "+f"((d)[3]) \
        : "r"((a)[0]), "r"((a)[1]), "r"((a)[2]), "r"((a)[3]), "r"(b0), "r"(b1))

// ---------------- prepass: split x -> bf16 hi/lo ------------------------------
__global__ void split_kernel(const float* __restrict__ in,
                             __nv_bfloat16* __restrict__ oh,
                             __nv_bfloat16* __restrict__ ol) {
    size_t i = ((size_t)blockIdx.x * blockDim.x + threadIdx.x) * 4;
    float4 v = *(const float4*)(in + i);
    __nv_bfloat16 h[4], l[4];
    split_bf(v.x, h[0], l[0]);
    split_bf(v.y, h[1], l[1]);
    split_bf(v.z, h[2], l[2]);
    split_bf(v.w, h[3], l[3]);
    *(uint2*)(oh + i) = *(uint2*)h;
    *(uint2*)(ol + i) = *(uint2*)l;
}

// ---------------- prepass: transpose + split weights -> bf16 [N][K] ----------
__global__ void transpose_split(const float* __restrict__ W,
                                __nv_bfloat16* __restrict__ Th,
                                __nv_bfloat16* __restrict__ Tl, int K, int N) {
    __shared__ float t[32][33];
    int kb = blockIdx.y * 32, nb = blockIdx.x * 32;
    for (int i = threadIdx.y; i < 32; i += 8)
        t[i][threadIdx.x] = W[(size_t)(kb + i) * N + nb + threadIdx.x];
    __syncthreads();
    for (int i = threadIdx.y; i < 32; i += 8) {
        float v = t[threadIdx.x][i];
        __nv_bfloat16 hi, lo;
        split_bf(v, hi, lo);
        size_t o = (size_t)(nb + i) * K + kb + threadIdx.x;
        Th[o] = hi;
        Tl[o] = lo;
    }
}

// ---------------- bf16x3 HMMA GEMM: C[M,N] = A @ Bt^T + bias -----------------
// CTA 128x128, BK=32, warps 2(m) x 4(n), warp tile 64x32.
// smem stage: Ah|Al|Bh|Bl each 128 rows x 64B (swizzled c16 ^= (row>>1)&3).
#define STAGE_B 32768
#define GEMM_SMEM (2 * STAGE_B)

__global__ __launch_bounds__(256, 1)
void gemm_mma(const __nv_bfloat16* __restrict__ Ah, const __nv_bfloat16* __restrict__ Al,
              const __nv_bfloat16* __restrict__ Bh, const __nv_bfloat16* __restrict__ Bl,
              const float* __restrict__ bias, float* __restrict__ C, int N)
{
    extern __shared__ char smem[];
    const uint32_t sbase = smem_u32(smem);
    const int tid = threadIdx.x;
    const int lane = tid & 31, wid = tid >> 5;
    const int wm = wid & 1, wn = wid >> 1;          // 2 x 4 warp grid
    const size_t m0 = (size_t)blockIdx.y * 128;
    const size_t n0 = (size_t)blockIdx.x * 128;

    // ---- gmem->smem stage loader: 512 rows of 64B (4 mats x 128 rows) ----
    const int rid0 = tid * 2;
    const int mat0 = rid0 >> 7, r0r = rid0 & 127;
    const int rid1 = tid * 2 + 1;
    const int mat1 = rid1 >> 7, r1r = rid1 & 127;

    const __nv_bfloat16* srcs[2];
    {
        const __nv_bfloat16* p;
        if (mat0 == 0)      p = Ah + (m0 + r0r) * KC;
        else if (mat0 == 1) p = Al + (m0 + r0r) * KC;
        else if (mat0 == 2) p = Bh + (n0 + r0r) * KC;
        else                p = Bl + (n0 + r0r) * KC;
        srcs[0] = p;
        if (mat1 == 0)      p = Ah + (m0 + r1r) * KC;
        else if (mat1 == 1) p = Al + (m0 + r1r) * KC;
        else if (mat1 == 2) p = Bh + (n0 + r1r) * KC;
        else                p = Bl + (n0 + r1r) * KC;
        srcs[1] = p;
    }
    const uint32_t dst0 = sbase + mat0 * 8192 + r0r * 64;
    const uint32_t dst1 = sbase + mat1 * 8192 + r1r * 64;
    const int sw0 = (r0r >> 1) & 3, sw1 = (r1r >> 1) & 3;

#define LOAD_STAGE(st, k0) do {                                              \
        uint32_t so = (uint32_t)(st) * STAGE_B;                              \
        const __nv_bfloat16* s0 = srcs[0] + (k0);                            \
        const __nv_bfloat16* s1 = srcs[1] + (k0);                            \
        _Pragma("unroll")                                                    \
        for (int c = 0; c < 4; c++) {                                        \
            CP_ASYNC16(dst0 + so + ((c ^ sw0) << 4), s0 + c * 8);            \
            CP_ASYNC16(dst1 + so + ((c ^ sw1) << 4), s1 + c * 8);            \
        }                                                                    \
    } while (0)

    float D[4][4][4];
#pragma unroll
    for (int i = 0; i < 4; i++)
#pragma unroll
        for (int j = 0; j < 4; j++)
#pragma unroll
            for (int c = 0; c < 4; c++) D[i][j][c] = 0.0f;

    LOAD_STAGE(0, 0);
    CP_COMMIT();

    const int NSTAGE = KC / 32;   // 16
#pragma unroll 1
    for (int s = 0; s < NSTAGE; s++) {
        if (s + 1 < NSTAGE) {
            LOAD_STAGE((s + 1) & 1, (s + 1) * 32);
            CP_COMMIT();
            CP_WAIT1();
        } else {
            CP_WAIT0();
        }
        __syncthreads();

        const uint32_t stb = sbase + (uint32_t)(s & 1) * STAGE_B;

#pragma unroll
        for (int slab = 0; slab < 2; slab++) {
            // A fragment addresses: row = tb + (lane&15), c16 = slab*2 + (lane>>4)
            uint32_t ah4[4][4], al4[4][4];
#pragma unroll
            for (int mi = 0; mi < 4; mi++) {
                int row = wm * 64 + mi * 16 + (lane & 15);
                int c16 = ((slab << 1) + (lane >> 4)) ^ ((row >> 1) & 3);
                uint32_t off = row * 64 + c16 * 16;
                LDM4(ah4[mi][0], ah4[mi][1], ah4[mi][2], ah4[mi][3], stb + off);
                LDM4(al4[mi][0], al4[mi][1], al4[mi][2], al4[mi][3], stb + 8192 + off);
            }
            // B fragments: row = tb + (lane&7) + (lane>>4)*8, c16 = slab*2 + ((lane>>3)&1)
            uint32_t bh4[2][4], bl4[2][4];
#pragma unroll
            for (int nj = 0; nj < 2; nj++) {
                int row = wn * 32 + nj * 16 + (lane & 7) + ((lane >> 4) << 3);
                int c16 = ((slab << 1) + ((lane >> 3) & 1)) ^ ((row >> 1) & 3);
                uint32_t off = row * 64 + c16 * 16;
                LDM4(bh4[nj][0], bh4[nj][1], bh4[nj][2], bh4[nj][3], stb + 16384 + off);
                LDM4(bl4[nj][0], bl4[nj][1], bl4[nj][2], bl4[nj][3], stb + 24576 + off);
            }
#pragma unroll
            for (int mi = 0; mi < 4; mi++) {
#pragma unroll
                for (int n8 = 0; n8 < 4; n8++) {
                    const int nj = n8 >> 1, hb = (n8 & 1) * 2;
                    MMA_BF16(D[mi][n8], ah4[mi], bh4[nj][hb], bh4[nj][hb + 1]);
                    MMA_BF16(D[mi][n8], al4[mi], bh4[nj][hb], bh4[nj][hb + 1]);
                    MMA_BF16(D[mi][n8], ah4[mi], bl4[nj][hb], bl4[nj][hb + 1]);
                }
            }
        }
        __syncthreads();
    }

    // ---- epilogue ----
    const int gr = lane >> 2, tg = lane & 3;
#pragma unroll
    for (int mi = 0; mi < 4; mi++) {
        size_t rowa = m0 + wm * 64 + mi * 16 + gr;
#pragma unroll
        for (int n8 = 0; n8 < 4; n8++) {
            int col = (int)n0 + wn * 32 + n8 * 8 + tg * 2;
            float b0v = bias[col], b1v = bias[col + 1];
            *(float2*)(C + rowa * N + col) =
                make_float2(D[mi][n8][0] + b0v, D[mi][n8][1] + b1v);
            *(float2*)(C + (rowa + 8) * N + col) =
                make_float2(D[mi][n8][2] + b0v, D[mi][n8][3] + b1v);
        }
    }
}

// ---------------- Window attention: one CTA per (head, window) --------------
#define QK_STRIDE 65
#define ATTN_SMEM_FLOATS (128 * QK_STRIDE * 2 + 128 * 64 + 128 * 128 + 256)
#define ATTN_SMEM_BYTES  (ATTN_SMEM_FLOATS * 4)

__global__ __launch_bounds__(256)
void attn_kernel(const float* __restrict__ qkv, const float* __restrict__ mask,
                 const float* __restrict__ btab,
                 __nv_bfloat16* __restrict__ att_hi, __nv_bfloat16* __restrict__ att_lo)
{
    const int h   = blockIdx.x;
    const int b   = blockIdx.y;
    const int tid = threadIdx.x;
    const int lane = tid & 31, warp = tid >> 5;
    const int ty = tid >> 4, tx = tid & 15;

    extern __shared__ float smf[];
    float* Qs = smf;
    float* Ks = Qs + 128 * QK_STRIDE;
    float* Vs = Ks + 128 * QK_STRIDE;
    float* Ss = Vs + 128 * 64;
    float* bs = Ss + 128 * 128;

    const size_t row0 = (size_t)b * WIN_;
    const float* qb = qkv + row0 * N1 + h * HDD;
    const float* kb = qb + CH;
    const float* vb = qb + 2 * CH;

    for (int i = tid; i < 128 * 16; i += 256) {
        int r = i >> 4, c4 = (i & 15) << 2;
        float4 q4 = *(const float4*)(qb + (size_t)r * N1 + c4);
        float4 k4 = *(const float4*)(kb + (size_t)r * N1 + c4);
        float4 v4 = *(const float4*)(vb + (size_t)r * N1 + c4);
        float* qd = Qs + r * QK_STRIDE + c4;
        qd[0] = q4.x; qd[1] = q4.y; qd[2] = q4.z; qd[3] = q4.w;
        float* kd = Ks + r * QK_STRIDE + c4;
        kd[0] = k4.x; kd[1] = k4.y; kd[2] = k4.z; kd[3] = k4.w;
        *(float4*)(Vs + r * 64 + c4) = v4;
    }
    if (tid < 255) bs[tid] = btab[tid * NHH + h];
    __syncthreads();

    float acc[8][8];
#pragma unroll
    for (int i = 0; i < 8; i++)
#pragma unroll
        for (int j = 0; j < 8; j++) acc[i][j] = 0.0f;

#pragma unroll 4
    for (int d = 0; d < 64; d++) {
        float qv[8], kv[8];
#pragma unroll
        for (int i = 0; i < 8; i++) qv[i] = Qs[(ty * 8 + i) * QK_STRIDE + d];
#pragma unroll
        for (int j = 0; j < 8; j++) kv[j] = Ks[(tx + 16 * j) * QK_STRIDE + d];
#pragma unroll
        for (int i = 0; i < 8; i++)
#pragma unroll
            for (int j = 0; j < 8; j++)
                acc[i][j] = fmaf(qv[i], kv[j], acc[i][j]);
    }

    const int wdw = b & 63;
    const float* mrow = mask + (size_t)wdw * (WIN_ * WIN_);
#pragma unroll
    for (int i = 0; i < 8; i++) {
        int q = ty * 8 + i;
#pragma unroll
        for (int j = 0; j < 8; j++) {
            int k = tx + 16 * j;
            Ss[q * 128 + k] = acc[i][j] * 0.125f + bs[k - q + 127] + mrow[q * 128 + k];
        }
    }
    __syncthreads();

    for (int qq = 0; qq < 16; qq++) {
        int q = warp * 16 + qq;
        float4 x = *(float4*)(Ss + q * 128 + lane * 4);
        float m = fmaxf(fmaxf(x.x, x.y), fmaxf(x.z, x.w));
#pragma unroll
        for (int o = 16; o; o >>= 1) m = fmaxf(m, __shfl_xor_sync(0xffffffffu, m, o));
        float e0 = expf(x.x - m), e1 = expf(x.y - m), e2 = expf(x.z - m), e3 = expf(x.w - m);
        float s = (e0 + e1) + (e2 + e3);
#pragma unroll
        for (int o = 16; o; o >>= 1) s += __shfl_xor_sync(0xffffffffu, s, o);
        float inv = 1.0f / s;
        *(float4*)(Ss + q * 128 + lane * 4) = make_float4(e0 * inv, e1 * inv, e2 * inv, e3 * inv);
    }
    __syncthreads();

    float o[8][4];
#pragma unroll
    for (int i = 0; i < 8; i++)
#pragma unroll
        for (int c = 0; c < 4; c++) o[i][c] = 0.0f;

#pragma unroll 2
    for (int k0 = 0; k0 < 128; k0 += 4) {
        float4 vv[4];
#pragma unroll
        for (int j = 0; j < 4; j++) vv[j] = *(const float4*)(Vs + (k0 + j) * 64 + tx * 4);
#pragma unroll
        for (int i = 0; i < 8; i++) {
            float4 p = *(const float4*)(Ss + (ty * 8 + i) * 128 + k0);
            o[i][0] = fmaf(p.x, vv[0].x, o[i][0]);
            o[i][1] = fmaf(p.x, vv[0].y, o[i][1]);
            o[i][2] = fmaf(p.x, vv[0].z, o[i][2]);
            o[i][3] = fmaf(p.x, vv[0].w, o[i][3]);
            o[i][0] = fmaf(p.y, vv[1].x, o[i][0]);
            o[i][1] = fmaf(p.y, vv[1].y, o[i][1]);
            o[i][2] = fmaf(p.y, vv[1].z, o[i][2]);
            o[i][3] = fmaf(p.y, vv[1].w, o[i][3]);
            o[i][0] = fmaf(p.z, vv[2].x, o[i][0]);
            o[i][1] = fmaf(p.z, vv[2].y, o[i][1]);
            o[i][2] = fmaf(p.z, vv[2].z, o[i][2]);
            o[i][3] = fmaf(p.z, vv[2].w, o[i][3]);
            o[i][0] = fmaf(p.w, vv[3].x, o[i][0]);
            o[i][1] = fmaf(p.w, vv[3].y, o[i][1]);
            o[i][2] = fmaf(p.w, vv[3].z, o[i][2]);
            o[i][3] = fmaf(p.w, vv[3].w, o[i][3]);
        }
    }

    __nv_bfloat16* ohb = att_hi + row0 * CH + h * HDD;
    __nv_bfloat16* olb = att_lo + row0 * CH + h * HDD;
#pragma unroll
    for (int i = 0; i < 8; i++) {
        __nv_bfloat16 hv[4], lv[4];
        split_bf(o[i][0], hv[0], lv[0]);
        split_bf(o[i][1], hv[1], lv[1]);
        split_bf(o[i][2], hv[2], lv[2]);
        split_bf(o[i][3], hv[3], lv[3]);
        size_t off = (size_t)(ty * 8 + i) * CH + tx * 4;
        *(uint2*)(ohb + off) = *(uint2*)hv;
        *(uint2*)(olb + off) = *(uint2*)lv;
    }
}

// ---------------- launch ----------------------------------------------------
extern "C" void kernel_launch(void* const* d_in, const int* in_sizes, int n_in,
                              void* d_out, int out_size)
{
    const float* x      = (const float*)d_in[0];
    const float* mask   = (const float*)d_in[1];
    const float* w_qkv  = (const float*)d_in[2];
    const float* b_qkv  = (const float*)d_in[3];
    const float* w_proj = (const float*)d_in[4];
    const float* b_proj = (const float*)d_in[5];
    const float* btab   = (const float*)d_in[6];
    float* out = (float*)d_out;

    float* qkv_s;
    __nv_bfloat16 *xh, *xl, *ah, *al, *wqh, *wql, *wph, *wpl;
    cudaGetSymbolAddress((void**)&qkv_s, g_qkv);
    cudaGetSymbolAddress((void**)&xh, g_xh);
    cudaGetSymbolAddress((void**)&xl, g_xl);
    cudaGetSymbolAddress((void**)&ah, g_ah);
    cudaGetSymbolAddress((void**)&al, g_al);
    cudaGetSymbolAddress((void**)&wqh, g_wqh);
    cudaGetSymbolAddress((void**)&wql, g_wql);
    cudaGetSymbolAddress((void**)&wph, g_wph);
    cudaGetSymbolAddress((void**)&wpl, g_wpl);

    cudaFuncSetAttribute(attn_kernel, cudaFuncAttributeMaxDynamicSharedMemorySize,
                         ATTN_SMEM_BYTES);
    cudaFuncSetAttribute(gemm_mma, cudaFuncAttributeMaxDynamicSharedMemorySize,
                         GEMM_SMEM);

    // prepass
    split_kernel<<<(MROWS * KC) / (256 * 4), 256>>>(x, xh, xl);
    transpose_split<<<dim3(N1 / 32, KC / 32), dim3(32, 8)>>>(w_qkv, wqh, wql, KC, N1);
    transpose_split<<<dim3(CH / 32, KC / 32), dim3(32, 8)>>>(w_proj, wph, wpl, KC, CH);

    // GEMM1: qkv = x @ w_qkv + b_qkv  (fp32 out)
    gemm_mma<<<dim3(N1 / 128, MROWS / 128), 256, GEMM_SMEM>>>(xh, xl, wqh, wql,
                                                              b_qkv, qkv_s, N1);
    // attention (bf16 hi/lo out)
    attn_kernel<<<dim3(NHH, BWT), 256, ATTN_SMEM_BYTES>>>(qkv_s, mask, btab, ah, al);
    // GEMM2: out = att @ w_proj + b_proj
    gemm_mma<<<dim3(CH / 128, MROWS / 128), 256, GEMM_SMEM>>>(ah, al, wph, wpl,
                                                              b_proj, out, CH);
}

// round 6
// speedup vs baseline: 1.5729x; 1.1405x over previous
#include <cuda_runtime.h>
#include <cuda_bf16.h>
#include <cstdint>
#include <cstddef>

// Problem constants
#define BWT   1024
#define WIN_  128
#define CH    512
#define NHH   8
#define HDD   64
#define MROWS (BWT * WIN_)   // 131072
#define N1    (3 * CH)       // 1536
#define KC    512

// ---------------- scratch (device globals) ----------------------------------
__device__ float         g_qkv[(size_t)MROWS * N1];   // fp32, feeds attention
__device__ __nv_bfloat16 g_xh[(size_t)MROWS * KC];
__device__ __nv_bfloat16 g_xl[(size_t)MROWS * KC];
__device__ __nv_bfloat16 g_ah[(size_t)MROWS * CH];    // attention out hi
__device__ __nv_bfloat16 g_al[(size_t)MROWS * CH];    // attention out lo
__device__ __nv_bfloat16 g_wqh[(size_t)N1 * KC];      // w_qkv^T  [N1][K]
__device__ __nv_bfloat16 g_wql[(size_t)N1 * KC];
__device__ __nv_bfloat16 g_wph[(size_t)CH * KC];      // w_proj^T [CH][K]
__device__ __nv_bfloat16 g_wpl[(size_t)CH * KC];

// ---------------- helpers ----------------------------------------------------
__device__ __forceinline__ uint32_t smem_u32(const void* p) {
    uint32_t a;
    asm("{ .reg .u64 t; cvta.to.shared.u64 t, %1; cvt.u32.u64 %0, t; }" : "=r"(a) : "l"(p));
    return a;
}
__device__ __forceinline__ void split_bf(float v, __nv_bfloat16& h, __nv_bfloat16& l) {
    h = __float2bfloat16_rn(v);
    l = __float2bfloat16_rn(v - __bfloat162float(h));
}

#define CP_ASYNC16(dst, src) \
    asm volatile("cp.async.cg.shared.global [%0], [%1], 16;" :: "r"(dst), "l"(src) : "memory")
#define CP_COMMIT()  asm volatile("cp.async.commit_group;" ::: "memory")
#define CP_WAIT1()   asm volatile("cp.async.wait_group 1;" ::: "memory")
#define CP_WAIT0()   asm volatile("cp.async.wait_group 0;" ::: "memory")

#define LDM4(r0, r1, r2, r3, addr) \
    asm volatile("ldmatrix.sync.aligned.m8n8.x4.shared.b16 {%0,%1,%2,%3}, [%4];" \
        : "=r"(r0), "=r"(r1), "=r"(r2), "=r"(r3) : "r"(addr))

#define MMA_BF16(d, a, b0, b1) \
    asm volatile("mma.sync.aligned.m16n8k16.row.col.f32.bf16.bf16.f32 " \
        "{%0,%1,%2,%3}, {%4,%5,%6,%7}, {%8,%9}, {%0,%1,%2,%3};" \
        : "+f"((d)[0]), "+f"((d)[1]), "+f"((d)[2]), "+f"((d)[3]) \
        : "r"((a)[0]), "r"((a)[1]), "r"((a)[2]), "r"((a)[3]), "r"(b0), "r"(b1))

// ---------------- prepass: split x -> bf16 hi/lo ------------------------------
__global__ void split_kernel(const float* __restrict__ in,
                             __nv_bfloat16* __restrict__ oh,
                             __nv_bfloat16* __restrict__ ol) {
    size_t i = ((size_t)blockIdx.x * blockDim.x + threadIdx.x) * 4;
    float4 v = *(const float4*)(in + i);
    __nv_bfloat16 h[4], l[4];
    split_bf(v.x, h[0], l[0]);
    split_bf(v.y, h[1], l[1]);
    split_bf(v.z, h[2], l[2]);
    split_bf(v.w, h[3], l[3]);
    *(uint2*)(oh + i) = *(uint2*)h;
    *(uint2*)(ol + i) = *(uint2*)l;
}

// ---------------- prepass: transpose + split weights -> bf16 [N][K] ----------
__global__ void transpose_split(const float* __restrict__ W,
                                __nv_bfloat16* __restrict__ Th,
                                __nv_bfloat16* __restrict__ Tl, int K, int N) {
    __shared__ float t[32][33];
    int kb = blockIdx.y * 32, nb = blockIdx.x * 32;
    for (int i = threadIdx.y; i < 32; i += 8)
        t[i][threadIdx.x] = W[(size_t)(kb + i) * N + nb + threadIdx.x];
    __syncthreads();
    for (int i = threadIdx.y; i < 32; i += 8) {
        float v = t[threadIdx.x][i];
        __nv_bfloat16 hi, lo;
        split_bf(v, hi, lo);
        size_t o = (size_t)(nb + i) * K + kb + threadIdx.x;
        Th[o] = hi;
        Tl[o] = lo;
    }
}

// ---------------- bf16x3 HMMA GEMM: C[M,N] = A @ Bt^T + bias -----------------
// CTA 128x128, BK=32, warps 2(m) x 4(n), warp tile 64x32.
// 3-stage cp.async pipeline (32KB/stage), 2 CTAs/SM.
// smem stage: Ah|Al|Bh|Bl each 128 rows x 64B (swizzled c16 ^= (row>>1)&3).
#define STAGE_B 32768
#define GEMM_SMEM (3 * STAGE_B)

__global__ __launch_bounds__(256, 2)
void gemm_mma(const __nv_bfloat16* __restrict__ Ah, const __nv_bfloat16* __restrict__ Al,
              const __nv_bfloat16* __restrict__ Bh, const __nv_bfloat16* __restrict__ Bl,
              const float* __restrict__ bias, float* __restrict__ C, int N)
{
    extern __shared__ char smem[];
    const uint32_t sbase = smem_u32(smem);
    const int tid = threadIdx.x;
    const int lane = tid & 31, wid = tid >> 5;
    const int wm = wid & 1, wn = wid >> 1;          // 2 x 4 warp grid
    const size_t m0 = (size_t)blockIdx.y * 128;
    const size_t n0 = (size_t)blockIdx.x * 128;

    // ---- gmem->smem stage loader: 512 rows of 64B (4 mats x 128 rows) ----
    const int rid0 = tid * 2;
    const int mat0 = rid0 >> 7, r0r = rid0 & 127;
    const int rid1 = tid * 2 + 1;
    const int mat1 = rid1 >> 7, r1r = rid1 & 127;

    const __nv_bfloat16* srcs[2];
    {
        const __nv_bfloat16* p;
        if (mat0 == 0)      p = Ah + (m0 + r0r) * KC;
        else if (mat0 == 1) p = Al + (m0 + r0r) * KC;
        else if (mat0 == 2) p = Bh + (n0 + r0r) * KC;
        else                p = Bl + (n0 + r0r) * KC;
        srcs[0] = p;
        if (mat1 == 0)      p = Ah + (m0 + r1r) * KC;
        else if (mat1 == 1) p = Al + (m0 + r1r) * KC;
        else if (mat1 == 2) p = Bh + (n0 + r1r) * KC;
        else                p = Bl + (n0 + r1r) * KC;
        srcs[1] = p;
    }
    const uint32_t dst0 = sbase + mat0 * 8192 + r0r * 64;
    const uint32_t dst1 = sbase + mat1 * 8192 + r1r * 64;
    const int sw0 = (r0r >> 1) & 3, sw1 = (r1r >> 1) & 3;

#define LOAD_STAGE(buf, k0) do {                                             \
        uint32_t so = (uint32_t)(buf) * STAGE_B;                             \
        const __nv_bfloat16* s0 = srcs[0] + (k0);                            \
        const __nv_bfloat16* s1 = srcs[1] + (k0);                            \
        _Pragma("unroll")                                                    \
        for (int c = 0; c < 4; c++) {                                        \
            CP_ASYNC16(dst0 + so + ((c ^ sw0) << 4), s0 + c * 8);            \
            CP_ASYNC16(dst1 + so + ((c ^ sw1) << 4), s1 + c * 8);            \
        }                                                                    \
    } while (0)

    float D[4][4][4];
#pragma unroll
    for (int i = 0; i < 4; i++)
#pragma unroll
        for (int j = 0; j < 4; j++)
#pragma unroll
            for (int c = 0; c < 4; c++) D[i][j][c] = 0.0f;

    LOAD_STAGE(0, 0);
    CP_COMMIT();
    LOAD_STAGE(1, 32);
    CP_COMMIT();

    const int NSTAGE = KC / 32;   // 16
    int buf = 0;
#pragma unroll 1
    for (int s = 0; s < NSTAGE; s++) {
        if (s + 1 < NSTAGE) { CP_WAIT1(); } else { CP_WAIT0(); }
        __syncthreads();    // all warps done with buf (s+2)%3's previous contents

        if (s + 2 < NSTAGE) {
            int nb = buf + 2; if (nb >= 3) nb -= 3;
            LOAD_STAGE(nb, (s + 2) * 32);
            CP_COMMIT();
        }

        const uint32_t stb = sbase + (uint32_t)buf * STAGE_B;

#pragma unroll
        for (int slab = 0; slab < 2; slab++) {
            // B fragments first (live across both A passes)
            uint32_t bh4[2][4], bl4[2][4];
#pragma unroll
            for (int nj = 0; nj < 2; nj++) {
                int row = wn * 32 + nj * 16 + (lane & 7) + ((lane >> 4) << 3);
                int c16 = ((slab << 1) + ((lane >> 3) & 1)) ^ ((row >> 1) & 3);
                uint32_t off = row * 64 + c16 * 16;
                LDM4(bh4[nj][0], bh4[nj][1], bh4[nj][2], bh4[nj][3], stb + 16384 + off);
                LDM4(bl4[nj][0], bl4[nj][1], bl4[nj][2], bl4[nj][3], stb + 24576 + off);
            }
            // A-hi pass: consume ah against bh and bl, then reuse regs for A-lo
            uint32_t fa[4][4];
#pragma unroll
            for (int mi = 0; mi < 4; mi++) {
                int row = wm * 64 + mi * 16 + (lane & 15);
                int c16 = ((slab << 1) + (lane >> 4)) ^ ((row >> 1) & 3);
                LDM4(fa[mi][0], fa[mi][1], fa[mi][2], fa[mi][3],
                     stb + row * 64 + c16 * 16);
            }
#pragma unroll
            for (int mi = 0; mi < 4; mi++)
#pragma unroll
                for (int n8 = 0; n8 < 4; n8++) {
                    const int nj = n8 >> 1, hb = (n8 & 1) * 2;
                    MMA_BF16(D[mi][n8], fa[mi], bh4[nj][hb], bh4[nj][hb + 1]);
                    MMA_BF16(D[mi][n8], fa[mi], bl4[nj][hb], bl4[nj][hb + 1]);
                }
            // A-lo pass
#pragma unroll
            for (int mi = 0; mi < 4; mi++) {
                int row = wm * 64 + mi * 16 + (lane & 15);
                int c16 = ((slab << 1) + (lane >> 4)) ^ ((row >> 1) & 3);
                LDM4(fa[mi][0], fa[mi][1], fa[mi][2], fa[mi][3],
                     stb + 8192 + row * 64 + c16 * 16);
            }
#pragma unroll
            for (int mi = 0; mi < 4; mi++)
#pragma unroll
                for (int n8 = 0; n8 < 4; n8++) {
                    const int nj = n8 >> 1, hb = (n8 & 1) * 2;
                    MMA_BF16(D[mi][n8], fa[mi], bh4[nj][hb], bh4[nj][hb + 1]);
                }
        }
        buf++; if (buf >= 3) buf -= 3;
    }

    // ---- epilogue ----
    const int gr = lane >> 2, tg = lane & 3;
#pragma unroll
    for (int mi = 0; mi < 4; mi++) {
        size_t rowa = m0 + wm * 64 + mi * 16 + gr;
#pragma unroll
        for (int n8 = 0; n8 < 4; n8++) {
            int col = (int)n0 + wn * 32 + n8 * 8 + tg * 2;
            float b0v = bias[col], b1v = bias[col + 1];
            *(float2*)(C + rowa * N + col) =
                make_float2(D[mi][n8][0] + b0v, D[mi][n8][1] + b1v);
            *(float2*)(C + (rowa + 8) * N + col) =
                make_float2(D[mi][n8][2] + b0v, D[mi][n8][3] + b1v);
        }
    }
}

// ---------------- Window attention: one CTA per (head, window) --------------
#define QK_STRIDE 65
#define ATTN_SMEM_FLOATS (128 * QK_STRIDE * 2 + 128 * 64 + 128 * 128 + 256)
#define ATTN_SMEM_BYTES  (ATTN_SMEM_FLOATS * 4)

__global__ __launch_bounds__(256)
void attn_kernel(const float* __restrict__ qkv, const float* __restrict__ mask,
                 const float* __restrict__ btab,
                 __nv_bfloat16* __restrict__ att_hi, __nv_bfloat16* __restrict__ att_lo)
{
    const int h   = blockIdx.x;
    const int b   = blockIdx.y;
    const int tid = threadIdx.x;
    const int lane = tid & 31, warp = tid >> 5;
    const int ty = tid >> 4, tx = tid & 15;

    extern __shared__ float smf[];
    float* Qs = smf;
    float* Ks = Qs + 128 * QK_STRIDE;
    float* Vs = Ks + 128 * QK_STRIDE;
    float* Ss = Vs + 128 * 64;
    float* bs = Ss + 128 * 128;

    const size_t row0 = (size_t)b * WIN_;
    const float* qb = qkv + row0 * N1 + h * HDD;
    const float* kb = qb + CH;
    const float* vb = qb + 2 * CH;

    for (int i = tid; i < 128 * 16; i += 256) {
        int r = i >> 4, c4 = (i & 15) << 2;
        float4 q4 = *(const float4*)(qb + (size_t)r * N1 + c4);
        float4 k4 = *(const float4*)(kb + (size_t)r * N1 + c4);
        float4 v4 = *(const float4*)(vb + (size_t)r * N1 + c4);
        float* qd = Qs + r * QK_STRIDE + c4;
        qd[0] = q4.x; qd[1] = q4.y; qd[2] = q4.z; qd[3] = q4.w;
        float* kd = Ks + r * QK_STRIDE + c4;
        kd[0] = k4.x; kd[1] = k4.y; kd[2] = k4.z; kd[3] = k4.w;
        *(float4*)(Vs + r * 64 + c4) = v4;
    }
    if (tid < 255) bs[tid] = btab[tid * NHH + h];
    __syncthreads();

    float acc[8][8];
#pragma unroll
    for (int i = 0; i < 8; i++)
#pragma unroll
        for (int j = 0; j < 8; j++) acc[i][j] = 0.0f;

#pragma unroll 4
    for (int d = 0; d < 64; d++) {
        float qv[8], kv[8];
#pragma unroll
        for (int i = 0; i < 8; i++) qv[i] = Qs[(ty * 8 + i) * QK_STRIDE + d];
#pragma unroll
        for (int j = 0; j < 8; j++) kv[j] = Ks[(tx + 16 * j) * QK_STRIDE + d];
#pragma unroll
        for (int i = 0; i < 8; i++)
#pragma unroll
            for (int j = 0; j < 8; j++)
                acc[i][j] = fmaf(qv[i], kv[j], acc[i][j]);
    }

    const int wdw = b & 63;
    const float* mrow = mask + (size_t)wdw * (WIN_ * WIN_);
#pragma unroll
    for (int i = 0; i < 8; i++) {
        int q = ty * 8 + i;
#pragma unroll
        for (int j = 0; j < 8; j++) {
            int k = tx + 16 * j;
            Ss[q * 128 + k] = acc[i][j] * 0.125f + bs[k - q + 127] + mrow[q * 128 + k];
        }
    }
    __syncthreads();

    for (int qq = 0; qq < 16; qq++) {
        int q = warp * 16 + qq;
        float4 x = *(float4*)(Ss + q * 128 + lane * 4);
        float m = fmaxf(fmaxf(x.x, x.y), fmaxf(x.z, x.w));
#pragma unroll
        for (int o = 16; o; o >>= 1) m = fmaxf(m, __shfl_xor_sync(0xffffffffu, m, o));
        float e0 = __expf(x.x - m), e1 = __expf(x.y - m);
        float e2 = __expf(x.z - m), e3 = __expf(x.w - m);
        float s = (e0 + e1) + (e2 + e3);
#pragma unroll
        for (int o = 16; o; o >>= 1) s += __shfl_xor_sync(0xffffffffu, s, o);
        float inv = 1.0f / s;
        *(float4*)(Ss + q * 128 + lane * 4) = make_float4(e0 * inv, e1 * inv, e2 * inv, e3 * inv);
    }
    __syncthreads();

    float o[8][4];
#pragma unroll
    for (int i = 0; i < 8; i++)
#pragma unroll
        for (int c = 0; c < 4; c++) o[i][c] = 0.0f;

#pragma unroll 2
    for (int k0 = 0; k0 < 128; k0 += 4) {
        float4 vv[4];
#pragma unroll
        for (int j = 0; j < 4; j++) vv[j] = *(const float4*)(Vs + (k0 + j) * 64 + tx * 4);
#pragma unroll
        for (int i = 0; i < 8; i++) {
            float4 p = *(const float4*)(Ss + (ty * 8 + i) * 128 + k0);
            o[i][0] = fmaf(p.x, vv[0].x, o[i][0]);
            o[i][1] = fmaf(p.x, vv[0].y, o[i][1]);
            o[i][2] = fmaf(p.x, vv[0].z, o[i][2]);
            o[i][3] = fmaf(p.x, vv[0].w, o[i][3]);
            o[i][0] = fmaf(p.y, vv[1].x, o[i][0]);
            o[i][1] = fmaf(p.y, vv[1].y, o[i][1]);
            o[i][2] = fmaf(p.y, vv[1].z, o[i][2]);
            o[i][3] = fmaf(p.y, vv[1].w, o[i][3]);
            o[i][0] = fmaf(p.z, vv[2].x, o[i][0]);
            o[i][1] = fmaf(p.z, vv[2].y, o[i][1]);
            o[i][2] = fmaf(p.z, vv[2].z, o[i][2]);
            o[i][3] = fmaf(p.z, vv[2].w, o[i][3]);
            o[i][0] = fmaf(p.w, vv[3].x, o[i][0]);
            o[i][1] = fmaf(p.w, vv[3].y, o[i][1]);
            o[i][2] = fmaf(p.w, vv[3].z, o[i][2]);
            o[i][3] = fmaf(p.w, vv[3].w, o[i][3]);
        }
    }

    __nv_bfloat16* ohb = att_hi + row0 * CH + h * HDD;
    __nv_bfloat16* olb = att_lo + row0 * CH + h * HDD;
#pragma unroll
    for (int i = 0; i < 8; i++) {
        __nv_bfloat16 hv[4], lv[4];
        split_bf(o[i][0], hv[0], lv[0]);
        split_bf(o[i][1], hv[1], lv[1]);
        split_bf(o[i][2], hv[2], lv[2]);
        split_bf(o[i][3], hv[3], lv[3]);
        size_t off = (size_t)(ty * 8 + i) * CH + tx * 4;
        *(uint2*)(ohb + off) = *(uint2*)hv;
        *(uint2*)(olb + off) = *(uint2*)lv;
    }
}

// ---------------- launch ----------------------------------------------------
extern "C" void kernel_launch(void* const* d_in, const int* in_sizes, int n_in,
                              void* d_out, int out_size)
{
    const float* x      = (const float*)d_in[0];
    const float* mask   = (const float*)d_in[1];
    const float* w_qkv  = (const float*)d_in[2];
    const float* b_qkv  = (const float*)d_in[3];
    const float* w_proj = (const float*)d_in[4];
    const float* b_proj = (const float*)d_in[5];
    const float* btab   = (const float*)d_in[6];
    float* out = (float*)d_out;

    float* qkv_s;
    __nv_bfloat16 *xh, *xl, *ah, *al, *wqh, *wql, *wph, *wpl;
    cudaGetSymbolAddress((void**)&qkv_s, g_qkv);
    cudaGetSymbolAddress((void**)&xh, g_xh);
    cudaGetSymbolAddress((void**)&xl, g_xl);
    cudaGetSymbolAddress((void**)&ah, g_ah);
    cudaGetSymbolAddress((void**)&al, g_al);
    cudaGetSymbolAddress((void**)&wqh, g_wqh);
    cudaGetSymbolAddress((void**)&wql, g_wql);
    cudaGetSymbolAddress((void**)&wph, g_wph);
    cudaGetSymbolAddress((void**)&wpl, g_wpl);

    cudaFuncSetAttribute(attn_kernel, cudaFuncAttributeMaxDynamicSharedMemorySize,
                         ATTN_SMEM_BYTES);
    cudaFuncSetAttribute(gemm_mma, cudaFuncAttributeMaxDynamicSharedMemorySize,
                         GEMM_SMEM);

    // prepass
    split_kernel<<<(MROWS * KC) / (256 * 4), 256>>>(x, xh, xl);
    transpose_split<<<dim3(N1 / 32, KC / 32), dim3(32, 8)>>>(w_qkv, wqh, wql, KC, N1);
    transpose_split<<<dim3(CH / 32, KC / 32), dim3(32, 8)>>>(w_proj, wph, wpl, KC, CH);

    // GEMM1: qkv = x @ w_qkv + b_qkv  (fp32 out)
    gemm_mma<<<dim3(N1 / 128, MROWS / 128), 256, GEMM_SMEM>>>(xh, xl, wqh, wql,
                                                              b_qkv, qkv_s, N1);
    // attention (bf16 hi/lo out)
    attn_kernel<<<dim3(NHH, BWT), 256, ATTN_SMEM_BYTES>>>(qkv_s, mask, btab, ah, al);
    // GEMM2: out = att @ w_proj + b_proj
    gemm_mma<<<dim3(CH / 128, MROWS / 128), 256, GEMM_SMEM>>>(ah, al, wph, wpl,
                                                              b_proj, out, CH);
}

// round 7
// speedup vs baseline: 2.4986x; 1.5885x over previous
#include <cuda_runtime.h>
#include <cuda_fp16.h>
#include <cstdint>
#include <cstddef>

// Problem constants
#define BWT   1024
#define WIN_  128
#define CH    512
#define NHH   8
#define HDD   64
#define MROWS (BWT * WIN_)   // 131072
#define N1    (3 * CH)       // 1536
#define KC    512

// ---------------- scratch (device globals) ----------------------------------
__device__ float  g_qkv[(size_t)MROWS * N1];   // fp32, feeds attention
__device__ __half g_xh[(size_t)MROWS * KC];
__device__ __half g_xl[(size_t)MROWS * KC];
__device__ __half g_ah[(size_t)MROWS * CH];    // attention out hi
__device__ __half g_al[(size_t)MROWS * CH];    // attention out lo
__device__ __half g_wqh[(size_t)N1 * KC];      // fp16(w_qkv^T)  [N1][K]
__device__ __half g_wph[(size_t)CH * KC];      // fp16(w_proj^T) [CH][K]

// ---------------- helpers ----------------------------------------------------
__device__ __forceinline__ uint32_t smem_u32(const void* p) {
    uint32_t a;
    asm("{ .reg .u64 t; cvta.to.shared.u64 t, %1; cvt.u32.u64 %0, t; }" : "=r"(a) : "l"(p));
    return a;
}
__device__ __forceinline__ void split_h(float v, __half& h, __half& l) {
    h = __float2half_rn(v);
    l = __float2half_rn(v - __half2float(h));
}

#define CP_ASYNC16(dst, src) \
    asm volatile("cp.async.cg.shared.global [%0], [%1], 16;" :: "r"(dst), "l"(src) : "memory")
#define CP_COMMIT()  asm volatile("cp.async.commit_group;" ::: "memory")
#define CP_WAIT2()   asm volatile("cp.async.wait_group 2;" ::: "memory")

#define LDM4(r0, r1, r2, r3, addr) \
    asm volatile("ldmatrix.sync.aligned.m8n8.x4.shared.b16 {%0,%1,%2,%3}, [%4];" \
        : "=r"(r0), "=r"(r1), "=r"(r2), "=r"(r3) : "r"(addr))

#define MMA_F16(d, a, b0, b1) \
    asm volatile("mma.sync.aligned.m16n8k16.row.col.f32.f16.f16.f32 " \
        "{%0,%1,%2,%3}, {%4,%5,%6,%7}, {%8,%9}, {%0,%1,%2,%3};" \
        : "+f"((d)[0]), "+f"((d)[1]), "+f"((d)[2]), "+f"((d)[3]) \
        : "r"((a)[0]), "r"((a)[1]), "r"((a)[2]), "r"((a)[3]), "r"(b0), "r"(b1))

// ---------------- prepass: split x -> fp16 hi/lo ------------------------------
__global__ void split_kernel(const float* __restrict__ in,
                             __half* __restrict__ oh, __half* __restrict__ ol) {
    size_t i = ((size_t)blockIdx.x * blockDim.x + threadIdx.x) * 4;
    float4 v = *(const float4*)(in + i);
    __half h[4], l[4];
    split_h(v.x, h[0], l[0]);
    split_h(v.y, h[1], l[1]);
    split_h(v.z, h[2], l[2]);
    split_h(v.w, h[3], l[3]);
    *(uint2*)(oh + i) = *(uint2*)h;
    *(uint2*)(ol + i) = *(uint2*)l;
}

// ---------------- prepass: transpose weights -> fp16 [N][K] -------------------
__global__ void transpose_h(const float* __restrict__ W,
                            __half* __restrict__ Th, int K, int N) {
    __shared__ float t[32][33];
    int kb = blockIdx.y * 32, nb = blockIdx.x * 32;
    for (int i = threadIdx.y; i < 32; i += 8)
        t[i][threadIdx.x] = W[(size_t)(kb + i) * N + nb + threadIdx.x];
    __syncthreads();
    for (int i = threadIdx.y; i < 32; i += 8)
        Th[(size_t)(nb + i) * K + kb + threadIdx.x] = __float2half_rn(t[threadIdx.x][i]);
}

// ---------------- fp16x2 HMMA GEMM: C[M,N] = (Ah+Al) @ Bh^T + bias -----------
// CTA 128x128, BK=32, warps 2(m) x 4(n), warp tile 64x32.
// 4-stage cp.async pipeline (24KB/stage), 2 CTAs/SM.
// stage layout: Ah (8KB) | Al (8KB) | Bh (8KB); rows 64B, swizzle c16 ^= (r>>1)&3.
#define STAGE_B 24576
#define GEMM_SMEM (4 * STAGE_B)

__global__ __launch_bounds__(256, 2)
void gemm_mma(const __half* __restrict__ Ah, const __half* __restrict__ Al,
              const __half* __restrict__ Bh,
              const float* __restrict__ bias, float* __restrict__ C, int N)
{
    extern __shared__ char smem[];
    const uint32_t sbase = smem_u32(smem);
    const int tid = threadIdx.x;
    const int lane = tid & 31, wid = tid >> 5;
    const int wm = wid & 1, wn = wid >> 1;          // 2 x 4 warp grid
    const size_t m0 = (size_t)blockIdx.y * 128;
    const size_t n0 = (size_t)blockIdx.x * 128;

    // ---- loader: 384 rows x 64B per stage = 1536 16B-chunks; 6 per thread ---
    const __half* srcp[6];
    uint32_t      dstp[6];
#pragma unroll
    for (int t = 0; t < 6; t++) {
        int g = tid + 256 * t;           // 0..1535
        int row = g >> 2, c = g & 3;     // row 0..383, 16B-chunk 0..3
        int mat = row >> 7, r = row & 127;
        const __half* base;
        if (mat == 0)      base = Ah + (m0 + r) * KC;
        else if (mat == 1) base = Al + (m0 + r) * KC;
        else               base = Bh + (n0 + r) * KC;
        srcp[t] = base + c * 8;
        dstp[t] = sbase + mat * 8192 + r * 64 + (uint32_t)((c ^ ((r >> 1) & 3)) << 4);
    }

#define LOAD_STAGE(buf, k0) do {                                   \
        uint32_t so = (uint32_t)(buf) * STAGE_B;                   \
        _Pragma("unroll")                                          \
        for (int t = 0; t < 6; t++)                                \
            CP_ASYNC16(dstp[t] + so, srcp[t] + (k0));              \
    } while (0)

    float D[4][4][4];
#pragma unroll
    for (int i = 0; i < 4; i++)
#pragma unroll
        for (int j = 0; j < 4; j++)
#pragma unroll
            for (int c = 0; c < 4; c++) D[i][j][c] = 0.0f;

    LOAD_STAGE(0, 0);  CP_COMMIT();
    LOAD_STAGE(1, 32); CP_COMMIT();
    LOAD_STAGE(2, 64); CP_COMMIT();

    const int NSTAGE = KC / 32;   // 16
    int buf = 0;
#pragma unroll 1
    for (int s = 0; s < NSTAGE; s++) {
        CP_WAIT2();          // oldest outstanding group (stage s) complete
        __syncthreads();

        if (s + 3 < NSTAGE) {
            LOAD_STAGE((buf + 3) & 3, (s + 3) * 32);
            CP_COMMIT();
        }

        const uint32_t stb = sbase + (uint32_t)buf * STAGE_B;

#pragma unroll
        for (int slab = 0; slab < 2; slab++) {
            // B fragments (live across both A passes)
            uint32_t bh4[2][4];
#pragma unroll
            for (int nj = 0; nj < 2; nj++) {
                int row = wn * 32 + nj * 16 + (lane & 7) + ((lane >> 4) << 3);
                int c16 = ((slab << 1) + ((lane >> 3) & 1)) ^ ((row >> 1) & 3);
                LDM4(bh4[nj][0], bh4[nj][1], bh4[nj][2], bh4[nj][3],
                     stb + 16384 + row * 64 + c16 * 16);
            }
            uint32_t fa[4][4];
            // A-hi pass
#pragma unroll
            for (int mi = 0; mi < 4; mi++) {
                int row = wm * 64 + mi * 16 + (lane & 15);
                int c16 = ((slab << 1) + (lane >> 4)) ^ ((row >> 1) & 3);
                LDM4(fa[mi][0], fa[mi][1], fa[mi][2], fa[mi][3],
                     stb + row * 64 + c16 * 16);
            }
#pragma unroll
            for (int mi = 0; mi < 4; mi++)
#pragma unroll
                for (int n8 = 0; n8 < 4; n8++) {
                    const int nj = n8 >> 1, hb = (n8 & 1) * 2;
                    MMA_F16(D[mi][n8], fa[mi], bh4[nj][hb], bh4[nj][hb + 1]);
                }
            // A-lo pass
#pragma unroll
            for (int mi = 0; mi < 4; mi++) {
                int row = wm * 64 + mi * 16 + (lane & 15);
                int c16 = ((slab << 1) + (lane >> 4)) ^ ((row >> 1) & 3);
                LDM4(fa[mi][0], fa[mi][1], fa[mi][2], fa[mi][3],
                     stb + 8192 + row * 64 + c16 * 16);
            }
#pragma unroll
            for (int mi = 0; mi < 4; mi++)
#pragma unroll
                for (int n8 = 0; n8 < 4; n8++) {
                    const int nj = n8 >> 1, hb = (n8 & 1) * 2;
                    MMA_F16(D[mi][n8], fa[mi], bh4[nj][hb], bh4[nj][hb + 1]);
                }
        }
        buf = (buf + 1) & 3;
    }

    // ---- epilogue ----
    const int gr = lane >> 2, tg = lane & 3;
#pragma unroll
    for (int mi = 0; mi < 4; mi++) {
        size_t rowa = m0 + wm * 64 + mi * 16 + gr;
#pragma unroll
        for (int n8 = 0; n8 < 4; n8++) {
            int col = (int)n0 + wn * 32 + n8 * 8 + tg * 2;
            float b0v = bias[col], b1v = bias[col + 1];
            *(float2*)(C + rowa * N + col) =
                make_float2(D[mi][n8][0] + b0v, D[mi][n8][1] + b1v);
            *(float2*)(C + (rowa + 8) * N + col) =
                make_float2(D[mi][n8][2] + b0v, D[mi][n8][3] + b1v);
        }
    }
}

// ---------------- Window attention: one CTA per (head, window) --------------
#define QK_STRIDE 65
#define ATTN_SMEM_FLOATS (128 * QK_STRIDE * 2 + 128 * 64 + 128 * 128 + 256)
#define ATTN_SMEM_BYTES  (ATTN_SMEM_FLOATS * 4)

__global__ __launch_bounds__(256)
void attn_kernel(const float* __restrict__ qkv, const float* __restrict__ mask,
                 const float* __restrict__ btab,
                 __half* __restrict__ att_hi, __half* __restrict__ att_lo)
{
    const int h   = blockIdx.x;
    const int b   = blockIdx.y;
    const int tid = threadIdx.x;
    const int lane = tid & 31, warp = tid >> 5;
    const int ty = tid >> 4, tx = tid & 15;

    extern __shared__ float smf[];
    float* Qs = smf;
    float* Ks = Qs + 128 * QK_STRIDE;
    float* Vs = Ks + 128 * QK_STRIDE;
    float* Ss = Vs + 128 * 64;
    float* bs = Ss + 128 * 128;

    const size_t row0 = (size_t)b * WIN_;
    const float* qb = qkv + row0 * N1 + h * HDD;
    const float* kb = qb + CH;
    const float* vb = qb + 2 * CH;

    for (int i = tid; i < 128 * 16; i += 256) {
        int r = i >> 4, c4 = (i & 15) << 2;
        float4 q4 = *(const float4*)(qb + (size_t)r * N1 + c4);
        float4 k4 = *(const float4*)(kb + (size_t)r * N1 + c4);
        float4 v4 = *(const float4*)(vb + (size_t)r * N1 + c4);
        float* qd = Qs + r * QK_STRIDE + c4;
        qd[0] = q4.x; qd[1] = q4.y; qd[2] = q4.z; qd[3] = q4.w;
        float* kd = Ks + r * QK_STRIDE + c4;
        kd[0] = k4.x; kd[1] = k4.y; kd[2] = k4.z; kd[3] = k4.w;
        *(float4*)(Vs + r * 64 + c4) = v4;
    }
    if (tid < 255) bs[tid] = btab[tid * NHH + h];
    __syncthreads();

    float acc[8][8];
#pragma unroll
    for (int i = 0; i < 8; i++)
#pragma unroll
        for (int j = 0; j < 8; j++) acc[i][j] = 0.0f;

#pragma unroll 4
    for (int d = 0; d < 64; d++) {
        float qv[8], kv[8];
#pragma unroll
        for (int i = 0; i < 8; i++) qv[i] = Qs[(ty * 8 + i) * QK_STRIDE + d];
#pragma unroll
        for (int j = 0; j < 8; j++) kv[j] = Ks[(tx + 16 * j) * QK_STRIDE + d];
#pragma unroll
        for (int i = 0; i < 8; i++)
#pragma unroll
            for (int j = 0; j < 8; j++)
                acc[i][j] = fmaf(qv[i], kv[j], acc[i][j]);
    }

    const int wdw = b & 63;
    const float* mrow = mask + (size_t)wdw * (WIN_ * WIN_);
#pragma unroll
    for (int i = 0; i < 8; i++) {
        int q = ty * 8 + i;
#pragma unroll
        for (int j = 0; j < 8; j++) {
            int k = tx + 16 * j;
            Ss[q * 128 + k] = acc[i][j] * 0.125f + bs[k - q + 127] + mrow[q * 128 + k];
        }
    }
    __syncthreads();

    for (int qq = 0; qq < 16; qq++) {
        int q = warp * 16 + qq;
        float4 x = *(float4*)(Ss + q * 128 + lane * 4);
        float m = fmaxf(fmaxf(x.x, x.y), fmaxf(x.z, x.w));
#pragma unroll
        for (int o = 16; o; o >>= 1) m = fmaxf(m, __shfl_xor_sync(0xffffffffu, m, o));
        float e0 = __expf(x.x - m), e1 = __expf(x.y - m);
        float e2 = __expf(x.z - m), e3 = __expf(x.w - m);
        float s = (e0 + e1) + (e2 + e3);
#pragma unroll
        for (int o = 16; o; o >>= 1) s += __shfl_xor_sync(0xffffffffu, s, o);
        float inv = 1.0f / s;
        *(float4*)(Ss + q * 128 + lane * 4) = make_float4(e0 * inv, e1 * inv, e2 * inv, e3 * inv);
    }
    __syncthreads();

    float o[8][4];
#pragma unroll
    for (int i = 0; i < 8; i++)
#pragma unroll
        for (int c = 0; c < 4; c++) o[i][c] = 0.0f;

#pragma unroll 2
    for (int k0 = 0; k0 < 128; k0 += 4) {
        float4 vv[4];
#pragma unroll
        for (int j = 0; j < 4; j++) vv[j] = *(const float4*)(Vs + (k0 + j) * 64 + tx * 4);
#pragma unroll
        for (int i = 0; i < 8; i++) {
            float4 p = *(const float4*)(Ss + (ty * 8 + i) * 128 + k0);
            o[i][0] = fmaf(p.x, vv[0].x, o[i][0]);
            o[i][1] = fmaf(p.x, vv[0].y, o[i][1]);
            o[i][2] = fmaf(p.x, vv[0].z, o[i][2]);
            o[i][3] = fmaf(p.x, vv[0].w, o[i][3]);
            o[i][0] = fmaf(p.y, vv[1].x, o[i][0]);
            o[i][1] = fmaf(p.y, vv[1].y, o[i][1]);
            o[i][2] = fmaf(p.y, vv[1].z, o[i][2]);
            o[i][3] = fmaf(p.y, vv[1].w, o[i][3]);
            o[i][0] = fmaf(p.z, vv[2].x, o[i][0]);
            o[i][1] = fmaf(p.z, vv[2].y, o[i][1]);
            o[i][2] = fmaf(p.z, vv[2].z, o[i][2]);
            o[i][3] = fmaf(p.z, vv[2].w, o[i][3]);
            o[i][0] = fmaf(p.w, vv[3].x, o[i][0]);
            o[i][1] = fmaf(p.w, vv[3].y, o[i][1]);
            o[i][2] = fmaf(p.w, vv[3].z, o[i][2]);
            o[i][3] = fmaf(p.w, vv[3].w, o[i][3]);
        }
    }

    __half* ohb = att_hi + row0 * CH + h * HDD;
    __half* olb = att_lo + row0 * CH + h * HDD;
#pragma unroll
    for (int i = 0; i < 8; i++) {
        __half hv[4], lv[4];
        split_h(o[i][0], hv[0], lv[0]);
        split_h(o[i][1], hv[1], lv[1]);
        split_h(o[i][2], hv[2], lv[2]);
        split_h(o[i][3], hv[3], lv[3]);
        size_t off = (size_t)(ty * 8 + i) * CH + tx * 4;
        *(uint2*)(ohb + off) = *(uint2*)hv;
        *(uint2*)(olb + off) = *(uint2*)lv;
    }
}

// ---------------- launch ----------------------------------------------------
extern "C" void kernel_launch(void* const* d_in, const int* in_sizes, int n_in,
                              void* d_out, int out_size)
{
    const float* x      = (const float*)d_in[0];
    const float* mask   = (const float*)d_in[1];
    const float* w_qkv  = (const float*)d_in[2];
    const float* b_qkv  = (const float*)d_in[3];
    const float* w_proj = (const float*)d_in[4];
    const float* b_proj = (const float*)d_in[5];
    const float* btab   = (const float*)d_in[6];
    float* out = (float*)d_out;

    float* qkv_s;
    __half *xh, *xl, *ah, *al, *wqh, *wph;
    cudaGetSymbolAddress((void**)&qkv_s, g_qkv);
    cudaGetSymbolAddress((void**)&xh, g_xh);
    cudaGetSymbolAddress((void**)&xl, g_xl);
    cudaGetSymbolAddress((void**)&ah, g_ah);
    cudaGetSymbolAddress((void**)&al, g_al);
    cudaGetSymbolAddress((void**)&wqh, g_wqh);
    cudaGetSymbolAddress((void**)&wph, g_wph);

    cudaFuncSetAttribute(attn_kernel, cudaFuncAttributeMaxDynamicSharedMemorySize,
                         ATTN_SMEM_BYTES);
    cudaFuncSetAttribute(gemm_mma, cudaFuncAttributeMaxDynamicSharedMemorySize,
                         GEMM_SMEM);

    // prepass
    split_kernel<<<(MROWS * KC) / (256 * 4), 256>>>(x, xh, xl);
    transpose_h<<<dim3(N1 / 32, KC / 32), dim3(32, 8)>>>(w_qkv, wqh, KC, N1);
    transpose_h<<<dim3(CH / 32, KC / 32), dim3(32, 8)>>>(w_proj, wph, KC, CH);

    // GEMM1: qkv = x @ w_qkv + b_qkv  (fp32 out)
    gemm_mma<<<dim3(N1 / 128, MROWS / 128), 256, GEMM_SMEM>>>(xh, xl, wqh,
                                                              b_qkv, qkv_s, N1);
    // attention (fp16 hi/lo out)
    attn_kernel<<<dim3(NHH, BWT), 256, ATTN_SMEM_BYTES>>>(qkv_s, mask, btab, ah, al);
    // GEMM2: out = att @ w_proj + b_proj
    gemm_mma<<<dim3(CH / 128, MROWS / 128), 256, GEMM_SMEM>>>(ah, al, wph,
                                                              b_proj, out, CH);
}

// round 8
// speedup vs baseline: 6.4615x; 2.5860x over previous
#include <cuda_runtime.h>
#include <cuda_fp16.h>
#include <cstdint>
#include <cstddef>

// Problem constants
#define BWT   1024
#define WIN_  128
#define CH    512
#define NHH   8
#define HDD   64
#define MROWS (BWT * WIN_)   // 131072
#define N1    (3 * CH)       // 1536
#define KC    512

// ---------------- scratch (device globals) ----------------------------------
__device__ __half g_qkvh[(size_t)MROWS * N1];  // fp16 qkv (GEMM1 out, attn in)
__device__ __half g_xh[(size_t)MROWS * KC];    // fp16(x)
__device__ __half g_ath[(size_t)MROWS * CH];   // fp16 attention out (GEMM2 in)
__device__ __half g_wqh[(size_t)N1 * KC];      // fp16(w_qkv^T)  [N1][K]
__device__ __half g_wph[(size_t)CH * KC];      // fp16(w_proj^T) [CH][K]

// ---------------- helpers ----------------------------------------------------
__device__ __forceinline__ uint32_t smem_u32(const void* p) {
    uint32_t a;
    asm("{ .reg .u64 t; cvta.to.shared.u64 t, %1; cvt.u32.u64 %0, t; }" : "=r"(a) : "l"(p));
    return a;
}

#define CP_ASYNC16(dst, src) \
    asm volatile("cp.async.cg.shared.global [%0], [%1], 16;" :: "r"(dst), "l"(src) : "memory")
#define CP_COMMIT()  asm volatile("cp.async.commit_group;" ::: "memory")
#define CP_WAIT2()   asm volatile("cp.async.wait_group 2;" ::: "memory")
#define CP_WAIT0()   asm volatile("cp.async.wait_group 0;" ::: "memory")

#define LDM4(r0, r1, r2, r3, addr) \
    asm volatile("ldmatrix.sync.aligned.m8n8.x4.shared.b16 {%0,%1,%2,%3}, [%4];" \
        : "=r"(r0), "=r"(r1), "=r"(r2), "=r"(r3) : "r"(addr))
#define LDM4T(r0, r1, r2, r3, addr) \
    asm volatile("ldmatrix.sync.aligned.m8n8.x4.trans.shared.b16 {%0,%1,%2,%3}, [%4];" \
        : "=r"(r0), "=r"(r1), "=r"(r2), "=r"(r3) : "r"(addr))

#define MMA_F16(d, a, b0, b1) \
    asm volatile("mma.sync.aligned.m16n8k16.row.col.f32.f16.f16.f32 " \
        "{%0,%1,%2,%3}, {%4,%5,%6,%7}, {%8,%9}, {%0,%1,%2,%3};" \
        : "+f"((d)[0]), "+f"((d)[1]), "+f"((d)[2]), "+f"((d)[3]) \
        : "r"((a)[0]), "r"((a)[1]), "r"((a)[2]), "r"((a)[3]), "r"(b0), "r"(b1))

__device__ __forceinline__ uint32_t h2u(float a, float b) {
    __half2 h = __floats2half2_rn(a, b);
    return *(uint32_t*)&h;
}
__device__ __forceinline__ void store2(float* p, float a, float b) {
    *(float2*)p = make_float2(a, b);
}
__device__ __forceinline__ void store2(__half* p, float a, float b) {
    *(__half2*)p = __floats2half2_rn(a, b);
}

// ---------------- prepass: x -> fp16 ------------------------------------------
__global__ void conv_h(const float* __restrict__ in, __half* __restrict__ o) {
    size_t i = ((size_t)blockIdx.x * blockDim.x + threadIdx.x) * 4;
    float4 v = *(const float4*)(in + i);
    __half h[4] = {__float2half_rn(v.x), __float2half_rn(v.y),
                   __float2half_rn(v.z), __float2half_rn(v.w)};
    *(uint2*)(o + i) = *(uint2*)h;
}

// ---------------- prepass: transpose weights -> fp16 [N][K] -------------------
__global__ void transpose_h(const float* __restrict__ W,
                            __half* __restrict__ Th, int K, int N) {
    __shared__ float t[32][33];
    int kb = blockIdx.y * 32, nb = blockIdx.x * 32;
    for (int i = threadIdx.y; i < 32; i += 8)
        t[i][threadIdx.x] = W[(size_t)(kb + i) * N + nb + threadIdx.x];
    __syncthreads();
    for (int i = threadIdx.y; i < 32; i += 8)
        Th[(size_t)(nb + i) * K + kb + threadIdx.x] = __float2half_rn(t[threadIdx.x][i]);
}

// ---------------- fp16 HMMA GEMM: C[M,N] = A @ Bt^T + bias -------------------
// CTA 128x128, BK=32, warps 2(m) x 4(n), 4-stage cp.async (16KB/stage).
#define STAGE_B 16384
#define GEMM_SMEM (4 * STAGE_B)

template <typename OutT>
__global__ __launch_bounds__(256, 2)
void gemm_mma(const __half* __restrict__ Ah, const __half* __restrict__ Bh,
              const float* __restrict__ bias, OutT* __restrict__ C, int N)
{
    extern __shared__ char smem[];
    const uint32_t sbase = smem_u32(smem);
    const int tid = threadIdx.x;
    const int lane = tid & 31, wid = tid >> 5;
    const int wm = wid & 1, wn = wid >> 1;          // 2 x 4 warp grid
    const size_t m0 = (size_t)blockIdx.y * 128;
    const size_t n0 = (size_t)blockIdx.x * 128;

    // loader: 256 rows x 64B per stage = 1024 16B-chunks; 4 per thread
    const __half* srcp[4];
    uint32_t      dstp[4];
#pragma unroll
    for (int t = 0; t < 4; t++) {
        int g = tid + 256 * t;
        int row = g >> 2, c = g & 3;
        int mat = row >> 7, r = row & 127;
        srcp[t] = (mat ? Bh + (n0 + r) * KC : Ah + (m0 + r) * KC) + c * 8;
        dstp[t] = sbase + mat * 8192 + r * 64 + (uint32_t)((c ^ ((r >> 1) & 3)) << 4);
    }

#define LOAD_STAGE(buf, k0) do {                                   \
        uint32_t so = (uint32_t)(buf) * STAGE_B;                   \
        _Pragma("unroll")                                          \
        for (int t = 0; t < 4; t++)                                \
            CP_ASYNC16(dstp[t] + so, srcp[t] + (k0));              \
    } while (0)

    float D[4][4][4];
#pragma unroll
    for (int i = 0; i < 4; i++)
#pragma unroll
        for (int j = 0; j < 4; j++)
#pragma unroll
            for (int c = 0; c < 4; c++) D[i][j][c] = 0.0f;

    LOAD_STAGE(0, 0);  CP_COMMIT();
    LOAD_STAGE(1, 32); CP_COMMIT();
    LOAD_STAGE(2, 64); CP_COMMIT();

    const int NSTAGE = KC / 32;   // 16
    int buf = 0;
#pragma unroll 1
    for (int s = 0; s < NSTAGE; s++) {
        CP_WAIT2();
        __syncthreads();

        if (s + 3 < NSTAGE) {
            LOAD_STAGE((buf + 3) & 3, (s + 3) * 32);
            CP_COMMIT();
        }

        const uint32_t stb = sbase + (uint32_t)buf * STAGE_B;

#pragma unroll
        for (int slab = 0; slab < 2; slab++) {
            uint32_t bh4[2][4];
#pragma unroll
            for (int nj = 0; nj < 2; nj++) {
                int row = wn * 32 + nj * 16 + (lane & 7) + ((lane >> 4) << 3);
                int c16 = ((slab << 1) + ((lane >> 3) & 1)) ^ ((row >> 1) & 3);
                LDM4(bh4[nj][0], bh4[nj][1], bh4[nj][2], bh4[nj][3],
                     stb + 8192 + row * 64 + c16 * 16);
            }
            uint32_t fa[4][4];
#pragma unroll
            for (int mi = 0; mi < 4; mi++) {
                int row = wm * 64 + mi * 16 + (lane & 15);
                int c16 = ((slab << 1) + (lane >> 4)) ^ ((row >> 1) & 3);
                LDM4(fa[mi][0], fa[mi][1], fa[mi][2], fa[mi][3],
                     stb + row * 64 + c16 * 16);
            }
#pragma unroll
            for (int mi = 0; mi < 4; mi++)
#pragma unroll
                for (int n8 = 0; n8 < 4; n8++) {
                    const int nj = n8 >> 1, hb = (n8 & 1) * 2;
                    MMA_F16(D[mi][n8], fa[mi], bh4[nj][hb], bh4[nj][hb + 1]);
                }
        }
        buf = (buf + 1) & 3;
    }

    // epilogue
    const int gr = lane >> 2, tg = lane & 3;
#pragma unroll
    for (int mi = 0; mi < 4; mi++) {
        size_t rowa = m0 + wm * 64 + mi * 16 + gr;
#pragma unroll
        for (int n8 = 0; n8 < 4; n8++) {
            int col = (int)n0 + wn * 32 + n8 * 8 + tg * 2;
            float b0v = bias[col], b1v = bias[col + 1];
            store2(C + rowa * N + col, D[mi][n8][0] + b0v, D[mi][n8][1] + b1v);
            store2(C + (rowa + 8) * N + col, D[mi][n8][2] + b0v, D[mi][n8][3] + b1v);
        }
    }
}

// ---------------- HMMA window attention: one CTA per (head, window) ----------
// 8 warps, each owns 16 q-rows. S=QK^T (f32 accum) -> bias+mask -> in-register
// softmax -> P(fp16, in-register) @ V -> fp16 out. smem: Q|K|V fp16 + bias.
#define ATTN_SMEM (3 * 16384 + 1024)

__global__ __launch_bounds__(256)
void attn_mma(const __half* __restrict__ qkv, const float* __restrict__ mask,
              const float* __restrict__ btab, __half* __restrict__ att)
{
    const int h = blockIdx.x;
    const int b = blockIdx.y;
    const int tid = threadIdx.x;
    const int lane = tid & 31, w = tid >> 5;
    const int gr = lane >> 2, tg = lane & 3;

    extern __shared__ char smc[];
    const uint32_t Qb = smem_u32(smc);
    const uint32_t Kb = Qb + 16384;
    const uint32_t Vb = Qb + 32768;
    float* bs = (float*)(smc + 49152);

    // ---- load Q,K,V fp16 into swizzled smem (rows 128B, chunk c ^ (r&7)) ----
    const size_t grow0 = (size_t)b * WIN_;
#pragma unroll
    for (int i = 0; i < 4; i++) {
        int g = tid + 256 * i;           // 0..1023
        int r = g >> 3, c = g & 7;
        const __half* src = qkv + (grow0 + r) * N1 + h * HDD + c * 8;
        uint32_t doff = r * 128 + (uint32_t)((c ^ (r & 7)) << 4);
        CP_ASYNC16(Qb + doff, src);
        CP_ASYNC16(Kb + doff, src + CH);
        CP_ASYNC16(Vb + doff, src + 2 * CH);
    }
    CP_COMMIT();
    if (tid < 255) bs[tid] = btab[tid * NHH + h];
    CP_WAIT0();
    __syncthreads();

    const int m0 = w * 16;
    const int r_lo = m0 + gr, r_hi = m0 + gr + 8;

    // ---- S = Q K^T ----
    float D[16][4];
#pragma unroll
    for (int j = 0; j < 16; j++)
#pragma unroll
        for (int c = 0; c < 4; c++) D[j][c] = 0.0f;

#pragma unroll
    for (int s = 0; s < 4; s++) {            // k16 over headdim
        uint32_t a[4];
        {
            int row = m0 + (lane & 15);
            int kc = (s << 1) + (lane >> 4);
            LDM4(a[0], a[1], a[2], a[3], Qb + row * 128 + ((kc ^ (row & 7)) << 4));
        }
#pragma unroll
        for (int jj = 0; jj < 8; jj++) {     // n16 over 128 k-positions
            uint32_t v0, v1, v2, v3;
            int grp = lane >> 3;
            int nrow = jj * 16 + ((grp >> 1) & 1) * 8 + (lane & 7);
            int kc = (s << 1) + (grp & 1);
            LDM4(v0, v1, v2, v3, Kb + nrow * 128 + ((kc ^ (nrow & 7)) << 4));
            MMA_F16(D[2 * jj], a, v0, v1);
            MMA_F16(D[2 * jj + 1], a, v2, v3);
        }
    }

    // ---- scale + rel-pos bias + window mask ----
    const float* mrow = mask + (size_t)(b & 63) * (WIN_ * WIN_);
#pragma unroll
    for (int j = 0; j < 16; j++) {
        int c = 8 * j + 2 * tg;
        float2 mlo2 = *(const float2*)(mrow + r_lo * 128 + c);
        float2 mhi2 = *(const float2*)(mrow + r_hi * 128 + c);
        D[j][0] = D[j][0] * 0.125f + bs[c - r_lo + 127] + mlo2.x;
        D[j][1] = D[j][1] * 0.125f + bs[c + 1 - r_lo + 127] + mlo2.y;
        D[j][2] = D[j][2] * 0.125f + bs[c - r_hi + 127] + mhi2.x;
        D[j][3] = D[j][3] * 0.125f + bs[c + 1 - r_hi + 127] + mhi2.y;
    }

    // ---- in-register softmax (rows r_lo and r_hi live across quad lanes) ----
    float mlo = -1e30f, mhi = -1e30f;
#pragma unroll
    for (int j = 0; j < 16; j++) {
        mlo = fmaxf(mlo, fmaxf(D[j][0], D[j][1]));
        mhi = fmaxf(mhi, fmaxf(D[j][2], D[j][3]));
    }
    mlo = fmaxf(mlo, __shfl_xor_sync(0xffffffffu, mlo, 1));
    mlo = fmaxf(mlo, __shfl_xor_sync(0xffffffffu, mlo, 2));
    mhi = fmaxf(mhi, __shfl_xor_sync(0xffffffffu, mhi, 1));
    mhi = fmaxf(mhi, __shfl_xor_sync(0xffffffffu, mhi, 2));

    float slo = 0.0f, shi = 0.0f;
#pragma unroll
    for (int j = 0; j < 16; j++) {
        D[j][0] = __expf(D[j][0] - mlo);
        D[j][1] = __expf(D[j][1] - mlo);
        D[j][2] = __expf(D[j][2] - mhi);
        D[j][3] = __expf(D[j][3] - mhi);
        slo += D[j][0] + D[j][1];
        shi += D[j][2] + D[j][3];
    }
    slo += __shfl_xor_sync(0xffffffffu, slo, 1);
    slo += __shfl_xor_sync(0xffffffffu, slo, 2);
    shi += __shfl_xor_sync(0xffffffffu, shi, 1);
    shi += __shfl_xor_sync(0xffffffffu, shi, 2);
    const float invlo = 1.0f / slo, invhi = 1.0f / shi;

    // ---- O = P V (P = unnormalized exp, fp16 in-register) ----
    float O[8][4];
#pragma unroll
    for (int j = 0; j < 8; j++)
#pragma unroll
        for (int c = 0; c < 4; c++) O[j][c] = 0.0f;

#pragma unroll
    for (int s = 0; s < 8; s++) {            // k16 over 128 tokens
        uint32_t a[4];
        a[0] = h2u(D[2 * s][0], D[2 * s][1]);
        a[1] = h2u(D[2 * s][2], D[2 * s][3]);
        a[2] = h2u(D[2 * s + 1][0], D[2 * s + 1][1]);
        a[3] = h2u(D[2 * s + 1][2], D[2 * s + 1][3]);
#pragma unroll
        for (int jj = 0; jj < 4; jj++) {     // n16 over headdim 64
            uint32_t v0, v1, v2, v3;
            int grp = lane >> 3;
            int krow = 16 * s + (grp & 1) * 8 + (lane & 7);
            int nc = (jj << 1) + ((grp >> 1) & 1);
            LDM4T(v0, v1, v2, v3, Vb + krow * 128 + ((nc ^ (krow & 7)) << 4));
            MMA_F16(O[2 * jj], a, v0, v1);
            MMA_F16(O[2 * jj + 1], a, v2, v3);
        }
    }

    // ---- epilogue: normalize + fp16 store ----
    __half* ob = att + grow0 * CH + h * HDD;
#pragma unroll
    for (int j = 0; j < 8; j++) {
        int c = 8 * j + 2 * tg;
        *(__half2*)(ob + (size_t)r_lo * CH + c) =
            __floats2half2_rn(O[j][0] * invlo, O[j][1] * invlo);
        *(__half2*)(ob + (size_t)r_hi * CH + c) =
            __floats2half2_rn(O[j][2] * invhi, O[j][3] * invhi);
    }
}

// ---------------- launch ----------------------------------------------------
extern "C" void kernel_launch(void* const* d_in, const int* in_sizes, int n_in,
                              void* d_out, int out_size)
{
    const float* x      = (const float*)d_in[0];
    const float* mask   = (const float*)d_in[1];
    const float* w_qkv  = (const float*)d_in[2];
    const float* b_qkv  = (const float*)d_in[3];
    const float* w_proj = (const float*)d_in[4];
    const float* b_proj = (const float*)d_in[5];
    const float* btab   = (const float*)d_in[6];
    float* out = (float*)d_out;

    __half *qkvh, *xh, *ath, *wqh, *wph;
    cudaGetSymbolAddress((void**)&qkvh, g_qkvh);
    cudaGetSymbolAddress((void**)&xh, g_xh);
    cudaGetSymbolAddress((void**)&ath, g_ath);
    cudaGetSymbolAddress((void**)&wqh, g_wqh);
    cudaGetSymbolAddress((void**)&wph, g_wph);

    cudaFuncSetAttribute(gemm_mma<__half>, cudaFuncAttributeMaxDynamicSharedMemorySize,
                         GEMM_SMEM);
    cudaFuncSetAttribute(gemm_mma<float>, cudaFuncAttributeMaxDynamicSharedMemorySize,
                         GEMM_SMEM);
    cudaFuncSetAttribute(attn_mma, cudaFuncAttributeMaxDynamicSharedMemorySize,
                         ATTN_SMEM);

    // prepass
    conv_h<<<(MROWS * KC) / (256 * 4), 256>>>(x, xh);
    transpose_h<<<dim3(N1 / 32, KC / 32), dim3(32, 8)>>>(w_qkv, wqh, KC, N1);
    transpose_h<<<dim3(CH / 32, KC / 32), dim3(32, 8)>>>(w_proj, wph, KC, CH);

    // GEMM1: qkv(fp16) = x @ w_qkv + b_qkv
    gemm_mma<__half><<<dim3(N1 / 128, MROWS / 128), 256, GEMM_SMEM>>>(
        xh, wqh, b_qkv, qkvh, N1);
    // attention (fp16 out)
    attn_mma<<<dim3(NHH, BWT), 256, ATTN_SMEM>>>(qkvh, mask, btab, ath);
    // GEMM2: out(fp32) = att @ w_proj + b_proj
    gemm_mma<float><<<dim3(CH / 128, MROWS / 128), 256, GEMM_SMEM>>>(
        ath, wph, b_proj, out, CH);
}

// round 9
// speedup vs baseline: 7.1628x; 1.1085x over previous
#include <cuda_runtime.h>
#include <cuda_fp16.h>
#include <cstdint>
#include <cstddef>

// Problem constants
#define BWT   1024
#define WIN_  128
#define CH    512
#define NHH   8
#define HDD   64
#define MROWS (BWT * WIN_)   // 131072
#define N1    (3 * CH)       // 1536
#define KC    512

// ---------------- scratch (device globals) ----------------------------------
__device__ __half g_qkvh[(size_t)MROWS * N1];  // fp16 qkv (GEMM1 out, attn in)
__device__ __half g_xh[(size_t)MROWS * KC];    // fp16(x)
__device__ __half g_ath[(size_t)MROWS * CH];   // fp16 attention out (GEMM2 in)
__device__ __half g_wqh[(size_t)N1 * KC];      // fp16(w_qkv^T)  [N1][K]
__device__ __half g_wph[(size_t)CH * KC];      // fp16(w_proj^T) [CH][K]

// ---------------- helpers ----------------------------------------------------
__device__ __forceinline__ uint32_t smem_u32(const void* p) {
    uint32_t a;
    asm("{ .reg .u64 t; cvta.to.shared.u64 t, %1; cvt.u32.u64 %0, t; }" : "=r"(a) : "l"(p));
    return a;
}

#define CP_ASYNC16(dst, src) \
    asm volatile("cp.async.cg.shared.global [%0], [%1], 16;" :: "r"(dst), "l"(src) : "memory")
#define CP_COMMIT()  asm volatile("cp.async.commit_group;" ::: "memory")
#define CP_WAIT1()   asm volatile("cp.async.wait_group 1;" ::: "memory")
#define CP_WAIT0()   asm volatile("cp.async.wait_group 0;" ::: "memory")

#define LDM4(r0, r1, r2, r3, addr) \
    asm volatile("ldmatrix.sync.aligned.m8n8.x4.shared.b16 {%0,%1,%2,%3}, [%4];" \
        : "=r"(r0), "=r"(r1), "=r"(r2), "=r"(r3) : "r"(addr))
#define LDM4T(r0, r1, r2, r3, addr) \
    asm volatile("ldmatrix.sync.aligned.m8n8.x4.trans.shared.b16 {%0,%1,%2,%3}, [%4];" \
        : "=r"(r0), "=r"(r1), "=r"(r2), "=r"(r3) : "r"(addr))

#define MMA_F16(d, a, b0, b1) \
    asm volatile("mma.sync.aligned.m16n8k16.row.col.f32.f16.f16.f32 " \
        "{%0,%1,%2,%3}, {%4,%5,%6,%7}, {%8,%9}, {%0,%1,%2,%3};" \
        : "+f"((d)[0]), "+f"((d)[1]), "+f"((d)[2]), "+f"((d)[3]) \
        : "r"((a)[0]), "r"((a)[1]), "r"((a)[2]), "r"((a)[3]), "r"(b0), "r"(b1))

__device__ __forceinline__ uint32_t h2u(float a, float b) {
    __half2 h = __floats2half2_rn(a, b);
    return *(uint32_t*)&h;
}
__device__ __forceinline__ void store2(float* p, float a, float b) {
    *(float2*)p = make_float2(a, b);
}
__device__ __forceinline__ void store2(__half* p, float a, float b) {
    *(__half2*)p = __floats2half2_rn(a, b);
}

// ---------------- prepass: x -> fp16 ------------------------------------------
__global__ void conv_h(const float* __restrict__ in, __half* __restrict__ o) {
    size_t i = ((size_t)blockIdx.x * blockDim.x + threadIdx.x) * 4;
    float4 v = *(const float4*)(in + i);
    __half h[4] = {__float2half_rn(v.x), __float2half_rn(v.y),
                   __float2half_rn(v.z), __float2half_rn(v.w)};
    *(uint2*)(o + i) = *(uint2*)h;
}

// ---------------- prepass: transpose weights -> fp16 [N][K] -------------------
__global__ void transpose_h(const float* __restrict__ W,
                            __half* __restrict__ Th, int K, int N) {
    __shared__ float t[32][33];
    int kb = blockIdx.y * 32, nb = blockIdx.x * 32;
    for (int i = threadIdx.y; i < 32; i += 8)
        t[i][threadIdx.x] = W[(size_t)(kb + i) * N + nb + threadIdx.x];
    __syncthreads();
    for (int i = threadIdx.y; i < 32; i += 8)
        Th[(size_t)(nb + i) * K + kb + threadIdx.x] = __float2half_rn(t[threadIdx.x][i]);
}

// ---------------- fp16 HMMA GEMM: C[M,N] = A @ Bt^T + bias -------------------
// CTA 128x128, BK=64, 128 threads (4 warps, 2x2 grid, warp tile 64x64).
// 3-stage cp.async pipeline (32KB/stage), 2 CTAs/SM.
// smem rows 128B (64 halves), swizzle: 16B chunk c stored at c ^ (row & 7).
#define STAGE_B 32768
#define GEMM_SMEM (3 * STAGE_B)

template <typename OutT>
__global__ __launch_bounds__(128, 2)
void gemm_mma(const __half* __restrict__ Ah, const __half* __restrict__ Bh,
              const float* __restrict__ bias, OutT* __restrict__ C, int N)
{
    extern __shared__ char smem[];
    const uint32_t sbase = smem_u32(smem);
    const int tid = threadIdx.x;
    const int lane = tid & 31, wid = tid >> 5;
    const int wm = wid & 1, wn = wid >> 1;          // 2 x 2 warp grid
    const size_t m0 = (size_t)blockIdx.y * 128;
    const size_t n0 = (size_t)blockIdx.x * 128;

    // loader: per stage 256 rows x 128B. Thread handles rows r0+16t (t=0..7)
    // for A and B; chunk c = tid&7 fixed; row&7 = r0&7 invariant across t.
    const int r0 = tid >> 3, c = tid & 7;
    const __half* srcA = Ah + (m0 + r0) * KC + c * 8;
    const __half* srcB = Bh + (n0 + r0) * KC + c * 8;
    const uint32_t dstA = sbase + r0 * 128 + (uint32_t)((c ^ (r0 & 7)) << 4);
    const uint32_t dstB = dstA + 16384;

#define LOAD_STAGE(buf, k0) do {                                       \
        uint32_t so = (uint32_t)(buf) * STAGE_B;                       \
        _Pragma("unroll")                                              \
        for (int t = 0; t < 8; t++) {                                  \
            CP_ASYNC16(dstA + so + t * 2048, srcA + (k0) + t * 16 * KC); \
            CP_ASYNC16(dstB + so + t * 2048, srcB + (k0) + t * 16 * KC); \
        }                                                              \
    } while (0)

    float D[4][8][4];
#pragma unroll
    for (int i = 0; i < 4; i++)
#pragma unroll
        for (int j = 0; j < 8; j++)
#pragma unroll
            for (int q = 0; q < 4; q++) D[i][j][q] = 0.0f;

    LOAD_STAGE(0, 0);  CP_COMMIT();
    LOAD_STAGE(1, 64); CP_COMMIT();

    const int NSTAGE = KC / 64;   // 8
#pragma unroll 1
    for (int s = 0; s < NSTAGE; s++) {
        if (s + 1 < NSTAGE) { CP_WAIT1(); } else { CP_WAIT0(); }
        __syncthreads();

        if (s + 2 < NSTAGE) {
            int nb = s + 2; nb -= (nb >= 3) ? 3 : 0; nb -= (nb >= 3) ? 3 : 0;
            LOAD_STAGE(nb, (s + 2) * 64);
            CP_COMMIT();
        }

        int bufc = s; bufc -= (bufc >= 3) ? 3 : 0; bufc -= (bufc >= 3) ? 3 : 0; bufc -= (bufc >= 3) ? 3 : 0;
        const uint32_t stb = sbase + (uint32_t)bufc * STAGE_B;

#pragma unroll
        for (int slab = 0; slab < 4; slab++) {
            uint32_t bh4[4][4];
#pragma unroll
            for (int nj = 0; nj < 4; nj++) {
                int row = wn * 64 + nj * 16 + (lane & 7) + ((lane >> 4) << 3);
                int kc = (slab << 1) + ((lane >> 3) & 1);
                LDM4(bh4[nj][0], bh4[nj][1], bh4[nj][2], bh4[nj][3],
                     stb + 16384 + row * 128 + ((kc ^ (row & 7)) << 4));
            }
            uint32_t fa[4][4];
#pragma unroll
            for (int mi = 0; mi < 4; mi++) {
                int row = wm * 64 + mi * 16 + (lane & 15);
                int kc = (slab << 1) + (lane >> 4);
                LDM4(fa[mi][0], fa[mi][1], fa[mi][2], fa[mi][3],
                     stb + row * 128 + ((kc ^ (row & 7)) << 4));
            }
#pragma unroll
            for (int mi = 0; mi < 4; mi++)
#pragma unroll
                for (int n8 = 0; n8 < 8; n8++) {
                    const int nj = n8 >> 1, hb = (n8 & 1) * 2;
                    MMA_F16(D[mi][n8], fa[mi], bh4[nj][hb], bh4[nj][hb + 1]);
                }
        }
    }

    // epilogue
    const int gr = lane >> 2, tg = lane & 3;
#pragma unroll
    for (int mi = 0; mi < 4; mi++) {
        size_t rowa = m0 + wm * 64 + mi * 16 + gr;
#pragma unroll
        for (int n8 = 0; n8 < 8; n8++) {
            int col = (int)n0 + wn * 64 + n8 * 8 + tg * 2;
            float b0v = bias[col], b1v = bias[col + 1];
            store2(C + rowa * N + col, D[mi][n8][0] + b0v, D[mi][n8][1] + b1v);
            store2(C + (rowa + 8) * N + col, D[mi][n8][2] + b0v, D[mi][n8][3] + b1v);
        }
    }
}

// ---------------- HMMA window attention: one CTA per (head, window) ----------
#define ATTN_SMEM (3 * 16384 + 1024)

__global__ __launch_bounds__(256)
void attn_mma(const __half* __restrict__ qkv, const float* __restrict__ mask,
              const float* __restrict__ btab, __half* __restrict__ att)
{
    const int h = blockIdx.x;
    const int b = blockIdx.y;
    const int tid = threadIdx.x;
    const int lane = tid & 31, w = tid >> 5;
    const int gr = lane >> 2, tg = lane & 3;

    extern __shared__ char smc[];
    const uint32_t Qb = smem_u32(smc);
    const uint32_t Kb = Qb + 16384;
    const uint32_t Vb = Qb + 32768;
    float* bs = (float*)(smc + 49152);

    const size_t grow0 = (size_t)b * WIN_;
#pragma unroll
    for (int i = 0; i < 4; i++) {
        int g = tid + 256 * i;
        int r = g >> 3, c = g & 7;
        const __half* src = qkv + (grow0 + r) * N1 + h * HDD + c * 8;
        uint32_t doff = r * 128 + (uint32_t)((c ^ (r & 7)) << 4);
        CP_ASYNC16(Qb + doff, src);
        CP_ASYNC16(Kb + doff, src + CH);
        CP_ASYNC16(Vb + doff, src + 2 * CH);
    }
    CP_COMMIT();
    if (tid < 255) bs[tid] = btab[tid * NHH + h];
    CP_WAIT0();
    __syncthreads();

    const int m0 = w * 16;
    const int r_lo = m0 + gr, r_hi = m0 + gr + 8;

    // ---- S = Q K^T ----
    float D[16][4];
#pragma unroll
    for (int j = 0; j < 16; j++)
#pragma unroll
        for (int c2 = 0; c2 < 4; c2++) D[j][c2] = 0.0f;

#pragma unroll
    for (int s = 0; s < 4; s++) {
        uint32_t a[4];
        {
            int row = m0 + (lane & 15);
            int kc = (s << 1) + (lane >> 4);
            LDM4(a[0], a[1], a[2], a[3], Qb + row * 128 + ((kc ^ (row & 7)) << 4));
        }
#pragma unroll
        for (int jj = 0; jj < 8; jj++) {
            uint32_t v0, v1, v2, v3;
            int grp = lane >> 3;
            int nrow = jj * 16 + ((grp >> 1) & 1) * 8 + (lane & 7);
            int kc = (s << 1) + (grp & 1);
            LDM4(v0, v1, v2, v3, Kb + nrow * 128 + ((kc ^ (nrow & 7)) << 4));
            MMA_F16(D[2 * jj], a, v0, v1);
            MMA_F16(D[2 * jj + 1], a, v2, v3);
        }
    }

    // ---- scale + rel-pos bias + window mask ----
    const float* mrow = mask + (size_t)(b & 63) * (WIN_ * WIN_);
#pragma unroll
    for (int j = 0; j < 16; j++) {
        int c = 8 * j + 2 * tg;
        float2 mlo2 = *(const float2*)(mrow + r_lo * 128 + c);
        float2 mhi2 = *(const float2*)(mrow + r_hi * 128 + c);
        D[j][0] = D[j][0] * 0.125f + bs[c - r_lo + 127] + mlo2.x;
        D[j][1] = D[j][1] * 0.125f + bs[c + 1 - r_lo + 127] + mlo2.y;
        D[j][2] = D[j][2] * 0.125f + bs[c - r_hi + 127] + mhi2.x;
        D[j][3] = D[j][3] * 0.125f + bs[c + 1 - r_hi + 127] + mhi2.y;
    }

    // ---- in-register softmax ----
    float mlo = -1e30f, mhi = -1e30f;
#pragma unroll
    for (int j = 0; j < 16; j++) {
        mlo = fmaxf(mlo, fmaxf(D[j][0], D[j][1]));
        mhi = fmaxf(mhi, fmaxf(D[j][2], D[j][3]));
    }
    mlo = fmaxf(mlo, __shfl_xor_sync(0xffffffffu, mlo, 1));
    mlo = fmaxf(mlo, __shfl_xor_sync(0xffffffffu, mlo, 2));
    mhi = fmaxf(mhi, __shfl_xor_sync(0xffffffffu, mhi, 1));
    mhi = fmaxf(mhi, __shfl_xor_sync(0xffffffffu, mhi, 2));

    float slo = 0.0f, shi = 0.0f;
#pragma unroll
    for (int j = 0; j < 16; j++) {
        D[j][0] = __expf(D[j][0] - mlo);
        D[j][1] = __expf(D[j][1] - mlo);
        D[j][2] = __expf(D[j][2] - mhi);
        D[j][3] = __expf(D[j][3] - mhi);
        slo += D[j][0] + D[j][1];
        shi += D[j][2] + D[j][3];
    }
    slo += __shfl_xor_sync(0xffffffffu, slo, 1);
    slo += __shfl_xor_sync(0xffffffffu, slo, 2);
    shi += __shfl_xor_sync(0xffffffffu, shi, 1);
    shi += __shfl_xor_sync(0xffffffffu, shi, 2);
    const float invlo = 1.0f / slo, invhi = 1.0f / shi;

    // ---- O = P V ----
    float O[8][4];
#pragma unroll
    for (int j = 0; j < 8; j++)
#pragma unroll
        for (int c2 = 0; c2 < 4; c2++) O[j][c2] = 0.0f;

#pragma unroll
    for (int s = 0; s < 8; s++) {
        uint32_t a[4];
        a[0] = h2u(D[2 * s][0], D[2 * s][1]);
        a[1] = h2u(D[2 * s][2], D[2 * s][3]);
        a[2] = h2u(D[2 * s + 1][0], D[2 * s + 1][1]);
        a[3] = h2u(D[2 * s + 1][2], D[2 * s + 1][3]);
#pragma unroll
        for (int jj = 0; jj < 4; jj++) {
            uint32_t v0, v1, v2, v3;
            int grp = lane >> 3;
            int krow = 16 * s + (grp & 1) * 8 + (lane & 7);
            int nc = (jj << 1) + ((grp >> 1) & 1);
            LDM4T(v0, v1, v2, v3, Vb + krow * 128 + ((nc ^ (krow & 7)) << 4));
            MMA_F16(O[2 * jj], a, v0, v1);
            MMA_F16(O[2 * jj + 1], a, v2, v3);
        }
    }

    __half* ob = att + grow0 * CH + h * HDD;
#pragma unroll
    for (int j = 0; j < 8; j++) {
        int c = 8 * j + 2 * tg;
        *(__half2*)(ob + (size_t)r_lo * CH + c) =
            __floats2half2_rn(O[j][0] * invlo, O[j][1] * invlo);
        *(__half2*)(ob + (size_t)r_hi * CH + c) =
            __floats2half2_rn(O[j][2] * invhi, O[j][3] * invhi);
    }
}

// ---------------- launch ----------------------------------------------------
extern "C" void kernel_launch(void* const* d_in, const int* in_sizes, int n_in,
                              void* d_out, int out_size)
{
    const float* x      = (const float*)d_in[0];
    const float* mask   = (const float*)d_in[1];
    const float* w_qkv  = (const float*)d_in[2];
    const float* b_qkv  = (const float*)d_in[3];
    const float* w_proj = (const float*)d_in[4];
    const float* b_proj = (const float*)d_in[5];
    const float* btab   = (const float*)d_in[6];
    float* out = (float*)d_out;

    __half *qkvh, *xh, *ath, *wqh, *wph;
    cudaGetSymbolAddress((void**)&qkvh, g_qkvh);
    cudaGetSymbolAddress((void**)&xh, g_xh);
    cudaGetSymbolAddress((void**)&ath, g_ath);
    cudaGetSymbolAddress((void**)&wqh, g_wqh);
    cudaGetSymbolAddress((void**)&wph, g_wph);

    cudaFuncSetAttribute(gemm_mma<__half>, cudaFuncAttributeMaxDynamicSharedMemorySize,
                         GEMM_SMEM);
    cudaFuncSetAttribute(gemm_mma<float>, cudaFuncAttributeMaxDynamicSharedMemorySize,
                         GEMM_SMEM);
    cudaFuncSetAttribute(attn_mma, cudaFuncAttributeMaxDynamicSharedMemorySize,
                         ATTN_SMEM);

    // prepass
    conv_h<<<(MROWS * KC) / (256 * 4), 256>>>(x, xh);
    transpose_h<<<dim3(N1 / 32, KC / 32), dim3(32, 8)>>>(w_qkv, wqh, KC, N1);
    transpose_h<<<dim3(CH / 32, KC / 32), dim3(32, 8)>>>(w_proj, wph, KC, CH);

    // GEMM1: qkv(fp16) = x @ w_qkv + b_qkv
    gemm_mma<__half><<<dim3(N1 / 128, MROWS / 128), 128, GEMM_SMEM>>>(
        xh, wqh, b_qkv, qkvh, N1);
    // attention (fp16 out)
    attn_mma<<<dim3(NHH, BWT), 256, ATTN_SMEM>>>(qkvh, mask, btab, ath);
    // GEMM2: out(fp32) = att @ w_proj + b_proj
    gemm_mma<float><<<dim3(CH / 128, MROWS / 128), 128, GEMM_SMEM>>>(
        ath, wph, b_proj, out, CH);
}

// round 10
// speedup vs baseline: 7.2346x; 1.0100x over previous
#include <cuda_runtime.h>
#include <cuda_fp16.h>
#include <cstdint>
#include <cstddef>

// Problem constants
#define BWT   1024
#define WIN_  128
#define CH    512
#define NHH   8
#define HDD   64
#define MROWS (BWT * WIN_)   // 131072
#define N1    (3 * CH)       // 1536
#define KC    512

// ---------------- scratch (device globals) ----------------------------------
__device__ __half g_qkvh[(size_t)MROWS * N1];  // fp16 qkv (GEMM1 out, attn in)
__device__ __half g_xh[(size_t)MROWS * KC];    // fp16(x)
__device__ __half g_ath[(size_t)MROWS * CH];   // fp16 attention out (GEMM2 in)
__device__ __half g_wqh[(size_t)N1 * KC];      // fp16(w_qkv^T)  [N1][K]
__device__ __half g_wph[(size_t)CH * KC];      // fp16(w_proj^T) [CH][K]

// ---------------- helpers ----------------------------------------------------
__device__ __forceinline__ uint32_t smem_u32(const void* p) {
    uint32_t a;
    asm("{ .reg .u64 t; cvta.to.shared.u64 t, %1; cvt.u32.u64 %0, t; }" : "=r"(a) : "l"(p));
    return a;
}

#define CP_ASYNC16(dst, src) \
    asm volatile("cp.async.cg.shared.global [%0], [%1], 16;" :: "r"(dst), "l"(src) : "memory")
#define CP_COMMIT()  asm volatile("cp.async.commit_group;" ::: "memory")
#define CP_WAIT1()   asm volatile("cp.async.wait_group 1;" ::: "memory")
#define CP_WAIT0()   asm volatile("cp.async.wait_group 0;" ::: "memory")

#define LDM4(r0, r1, r2, r3, addr) \
    asm volatile("ldmatrix.sync.aligned.m8n8.x4.shared.b16 {%0,%1,%2,%3}, [%4];" \
        : "=r"(r0), "=r"(r1), "=r"(r2), "=r"(r3) : "r"(addr))
#define LDM4T(r0, r1, r2, r3, addr) \
    asm volatile("ldmatrix.sync.aligned.m8n8.x4.trans.shared.b16 {%0,%1,%2,%3}, [%4];" \
        : "=r"(r0), "=r"(r1), "=r"(r2), "=r"(r3) : "r"(addr))

#define MMA_F16(d, a, b0, b1) \
    asm volatile("mma.sync.aligned.m16n8k16.row.col.f32.f16.f16.f32 " \
        "{%0,%1,%2,%3}, {%4,%5,%6,%7}, {%8,%9}, {%0,%1,%2,%3};" \
        : "+f"((d)[0]), "+f"((d)[1]), "+f"((d)[2]), "+f"((d)[3]) \
        : "r"((a)[0]), "r"((a)[1]), "r"((a)[2]), "r"((a)[3]), "r"(b0), "r"(b1))

__device__ __forceinline__ uint32_t h2u(float a, float b) {
    __half2 h = __floats2half2_rn(a, b);
    return *(uint32_t*)&h;
}
__device__ __forceinline__ void store2(float* p, float a, float b) {
    *(float2*)p = make_float2(a, b);
}
__device__ __forceinline__ void store2(__half* p, float a, float b) {
    *(__half2*)p = __floats2half2_rn(a, b);
}

// ---------------- prepass: x -> fp16 ------------------------------------------
__global__ void conv_h(const float* __restrict__ in, __half* __restrict__ o) {
    size_t i = ((size_t)blockIdx.x * blockDim.x + threadIdx.x) * 4;
    float4 v = *(const float4*)(in + i);
    __half h[4] = {__float2half_rn(v.x), __float2half_rn(v.y),
                   __float2half_rn(v.z), __float2half_rn(v.w)};
    *(uint2*)(o + i) = *(uint2*)h;
}

// ---------------- prepass: transpose weights -> fp16 [N][K] -------------------
__global__ void transpose_h(const float* __restrict__ W,
                            __half* __restrict__ Th, int K, int N) {
    __shared__ float t[32][33];
    int kb = blockIdx.y * 32, nb = blockIdx.x * 32;
    for (int i = threadIdx.y; i < 32; i += 8)
        t[i][threadIdx.x] = W[(size_t)(kb + i) * N + nb + threadIdx.x];
    __syncthreads();
    for (int i = threadIdx.y; i < 32; i += 8)
        Th[(size_t)(nb + i) * K + kb + threadIdx.x] = __float2half_rn(t[threadIdx.x][i]);
}

// ---------------- fp16 HMMA GEMM: C[M,N] = A @ Bt^T + bias -------------------
// CTA 128x128, BK=64, 128 threads (4 warps, 2x2 grid, warp tile 64x64).
// 3-stage cp.async pipeline (32KB/stage), 2 CTAs/SM.
// Register-level fragment double buffering: LDSMs for slab k+1 issued before
// the MMAs of slab k, hiding LDSM latency under tensor work.
#define STAGE_B 32768
#define GEMM_SMEM (3 * STAGE_B)

template <typename OutT>
__global__ __launch_bounds__(128, 2)
void gemm_mma(const __half* __restrict__ Ah, const __half* __restrict__ Bh,
              const float* __restrict__ bias, OutT* __restrict__ C, int N)
{
    extern __shared__ char smem[];
    const uint32_t sbase = smem_u32(smem);
    const int tid = threadIdx.x;
    const int lane = tid & 31, wid = tid >> 5;
    const int wm = wid & 1, wn = wid >> 1;          // 2 x 2 warp grid
    const size_t m0 = (size_t)blockIdx.y * 128;
    const size_t n0 = (size_t)blockIdx.x * 128;

    // loader: per stage 256 rows x 128B; thread handles rows r0+16t, chunk c.
    const int r0 = tid >> 3, c = tid & 7;
    const __half* srcA = Ah + (m0 + r0) * KC + c * 8;
    const __half* srcB = Bh + (n0 + r0) * KC + c * 8;
    const uint32_t dstA = sbase + r0 * 128 + (uint32_t)((c ^ (r0 & 7)) << 4);
    const uint32_t dstB = dstA + 16384;

#define LOAD_STAGE(buf, k0) do {                                       \
        uint32_t so = (uint32_t)(buf) * STAGE_B;                       \
        _Pragma("unroll")                                              \
        for (int t = 0; t < 8; t++) {                                  \
            CP_ASYNC16(dstA + so + t * 2048, srcA + (k0) + t * 16 * KC); \
            CP_ASYNC16(dstB + so + t * 2048, srcB + (k0) + t * 16 * KC); \
        }                                                              \
    } while (0)

    // fragment loads for one k16 slab
    const int arow = wm * 64 + (lane & 15);
    const int brow_ = wn * 64 + (lane & 7) + ((lane >> 4) << 3);
#define LD_AFRAG(fa, stb, slab) do {                                       \
        _Pragma("unroll")                                                  \
        for (int mi = 0; mi < 4; mi++) {                                   \
            int row = arow + mi * 16;                                      \
            int kc = ((slab) << 1) + (lane >> 4);                          \
            LDM4((fa)[mi][0], (fa)[mi][1], (fa)[mi][2], (fa)[mi][3],       \
                 (stb) + row * 128 + ((kc ^ (row & 7)) << 4));             \
        }                                                                  \
    } while (0)
#define LD_BFRAG(bh, stb, slab) do {                                       \
        _Pragma("unroll")                                                  \
        for (int nj = 0; nj < 4; nj++) {                                   \
            int row = brow_ + nj * 16;                                     \
            int kc = ((slab) << 1) + ((lane >> 3) & 1);                    \
            LDM4((bh)[nj][0], (bh)[nj][1], (bh)[nj][2], (bh)[nj][3],       \
                 (stb) + 16384 + row * 128 + ((kc ^ (row & 7)) << 4));     \
        }                                                                  \
    } while (0)

    float D[4][8][4];
#pragma unroll
    for (int i = 0; i < 4; i++)
#pragma unroll
        for (int j = 0; j < 8; j++)
#pragma unroll
            for (int q = 0; q < 4; q++) D[i][j][q] = 0.0f;

    LOAD_STAGE(0, 0);  CP_COMMIT();
    LOAD_STAGE(1, 64); CP_COMMIT();

    uint32_t fa[2][4][4], fb[2][4][4];

    const int NSTAGE = KC / 64;   // 8
#pragma unroll 1
    for (int s = 0; s < NSTAGE; s++) {
        if (s + 1 < NSTAGE) { CP_WAIT1(); } else { CP_WAIT0(); }
        __syncthreads();

        int bufc = s; bufc -= (bufc >= 3) ? 3 : 0; bufc -= (bufc >= 3) ? 3 : 0;
        bufc -= (bufc >= 3) ? 3 : 0;
        const uint32_t stb = sbase + (uint32_t)bufc * STAGE_B;

        // preload slab 0 fragments, then issue next-stage gmem loads under them
        LD_BFRAG(fb[0], stb, 0);
        LD_AFRAG(fa[0], stb, 0);

        if (s + 2 < NSTAGE) {
            int nb = s + 2; nb -= (nb >= 3) ? 3 : 0; nb -= (nb >= 3) ? 3 : 0;
            LOAD_STAGE(nb, (s + 2) * 64);
            CP_COMMIT();
        }

#pragma unroll
        for (int slab = 0; slab < 4; slab++) {
            const int cur = slab & 1, nxt = cur ^ 1;
            if (slab < 3) {
                LD_BFRAG(fb[nxt], stb, slab + 1);
                LD_AFRAG(fa[nxt], stb, slab + 1);
            }
#pragma unroll
            for (int mi = 0; mi < 4; mi++)
#pragma unroll
                for (int n8 = 0; n8 < 8; n8++) {
                    const int nj = n8 >> 1, hb = (n8 & 1) * 2;
                    MMA_F16(D[mi][n8], fa[cur][mi], fb[cur][nj][hb], fb[cur][nj][hb + 1]);
                }
        }
    }

    // epilogue
    const int gr = lane >> 2, tg = lane & 3;
#pragma unroll
    for (int mi = 0; mi < 4; mi++) {
        size_t rowa = m0 + wm * 64 + mi * 16 + gr;
#pragma unroll
        for (int n8 = 0; n8 < 8; n8++) {
            int col = (int)n0 + wn * 64 + n8 * 8 + tg * 2;
            float b0v = bias[col], b1v = bias[col + 1];
            store2(C + rowa * N + col, D[mi][n8][0] + b0v, D[mi][n8][1] + b1v);
            store2(C + (rowa + 8) * N + col, D[mi][n8][2] + b0v, D[mi][n8][3] + b1v);
        }
    }
}

// ---------------- HMMA window attention: one CTA per (head, window) ----------
#define ATTN_SMEM (3 * 16384 + 1024)

__global__ __launch_bounds__(256)
void attn_mma(const __half* __restrict__ qkv, const float* __restrict__ mask,
              const float* __restrict__ btab, __half* __restrict__ att)
{
    const int h = blockIdx.x;
    const int b = blockIdx.y;
    const int tid = threadIdx.x;
    const int lane = tid & 31, w = tid >> 5;
    const int gr = lane >> 2, tg = lane & 3;

    extern __shared__ char smc[];
    const uint32_t Qb = smem_u32(smc);
    const uint32_t Kb = Qb + 16384;
    const uint32_t Vb = Qb + 32768;
    float* bs = (float*)(smc + 49152);

    const size_t grow0 = (size_t)b * WIN_;
#pragma unroll
    for (int i = 0; i < 4; i++) {
        int g = tid + 256 * i;
        int r = g >> 3, c = g & 7;
        const __half* src = qkv + (grow0 + r) * N1 + h * HDD + c * 8;
        uint32_t doff = r * 128 + (uint32_t)((c ^ (r & 7)) << 4);
        CP_ASYNC16(Qb + doff, src);
        CP_ASYNC16(Kb + doff, src + CH);
        CP_ASYNC16(Vb + doff, src + 2 * CH);
    }
    CP_COMMIT();
    if (tid < 255) bs[tid] = btab[tid * NHH + h];
    CP_WAIT0();
    __syncthreads();

    const int m0 = w * 16;
    const int r_lo = m0 + gr, r_hi = m0 + gr + 8;

    // ---- S = Q K^T ----
    float D[16][4];
#pragma unroll
    for (int j = 0; j < 16; j++)
#pragma unroll
        for (int c2 = 0; c2 < 4; c2++) D[j][c2] = 0.0f;

#pragma unroll
    for (int s = 0; s < 4; s++) {
        uint32_t a[4];
        {
            int row = m0 + (lane & 15);
            int kc = (s << 1) + (lane >> 4);
            LDM4(a[0], a[1], a[2], a[3], Qb + row * 128 + ((kc ^ (row & 7)) << 4));
        }
#pragma unroll
        for (int jj = 0; jj < 8; jj++) {
            uint32_t v0, v1, v2, v3;
            int grp = lane >> 3;
            int nrow = jj * 16 + ((grp >> 1) & 1) * 8 + (lane & 7);
            int kc = (s << 1) + (grp & 1);
            LDM4(v0, v1, v2, v3, Kb + nrow * 128 + ((kc ^ (nrow & 7)) << 4));
            MMA_F16(D[2 * jj], a, v0, v1);
            MMA_F16(D[2 * jj + 1], a, v2, v3);
        }
    }

    // ---- scale + rel-pos bias + window mask ----
    const float* mrow = mask + (size_t)(b & 63) * (WIN_ * WIN_);
#pragma unroll
    for (int j = 0; j < 16; j++) {
        int c = 8 * j + 2 * tg;
        float2 mlo2 = *(const float2*)(mrow + r_lo * 128 + c);
        float2 mhi2 = *(const float2*)(mrow + r_hi * 128 + c);
        D[j][0] = D[j][0] * 0.125f + bs[c - r_lo + 127] + mlo2.x;
        D[j][1] = D[j][1] * 0.125f + bs[c + 1 - r_lo + 127] + mlo2.y;
        D[j][2] = D[j][2] * 0.125f + bs[c - r_hi + 127] + mhi2.x;
        D[j][3] = D[j][3] * 0.125f + bs[c + 1 - r_hi + 127] + mhi2.y;
    }

    // ---- in-register softmax ----
    float mlo = -1e30f, mhi = -1e30f;
#pragma unroll
    for (int j = 0; j < 16; j++) {
        mlo = fmaxf(mlo, fmaxf(D[j][0], D[j][1]));
        mhi = fmaxf(mhi, fmaxf(D[j][2], D[j][3]));
    }
    mlo = fmaxf(mlo, __shfl_xor_sync(0xffffffffu, mlo, 1));
    mlo = fmaxf(mlo, __shfl_xor_sync(0xffffffffu, mlo, 2));
    mhi = fmaxf(mhi, __shfl_xor_sync(0xffffffffu, mhi, 1));
    mhi = fmaxf(mhi, __shfl_xor_sync(0xffffffffu, mhi, 2));

    float slo = 0.0f, shi = 0.0f;
#pragma unroll
    for (int j = 0; j < 16; j++) {
        D[j][0] = __expf(D[j][0] - mlo);
        D[j][1] = __expf(D[j][1] - mlo);
        D[j][2] = __expf(D[j][2] - mhi);
        D[j][3] = __expf(D[j][3] - mhi);
        slo += D[j][0] + D[j][1];
        shi += D[j][2] + D[j][3];
    }
    slo += __shfl_xor_sync(0xffffffffu, slo, 1);
    slo += __shfl_xor_sync(0xffffffffu, slo, 2);
    shi += __shfl_xor_sync(0xffffffffu, shi, 1);
    shi += __shfl_xor_sync(0xffffffffu, shi, 2);
    const float invlo = 1.0f / slo, invhi = 1.0f / shi;

    // ---- O = P V ----
    float O[8][4];
#pragma unroll
    for (int j = 0; j < 8; j++)
#pragma unroll
        for (int c2 = 0; c2 < 4; c2++) O[j][c2] = 0.0f;

#pragma unroll
    for (int s = 0; s < 8; s++) {
        uint32_t a[4];
        a[0] = h2u(D[2 * s][0], D[2 * s][1]);
        a[1] = h2u(D[2 * s][2], D[2 * s][3]);
        a[2] = h2u(D[2 * s + 1][0], D[2 * s + 1][1]);
        a[3] = h2u(D[2 * s + 1][2], D[2 * s + 1][3]);
#pragma unroll
        for (int jj = 0; jj < 4; jj++) {
            uint32_t v0, v1, v2, v3;
            int grp = lane >> 3;
            int krow = 16 * s + (grp & 1) * 8 + (lane & 7);
            int nc = (jj << 1) + ((grp >> 1) & 1);
            LDM4T(v0, v1, v2, v3, Vb + krow * 128 + ((nc ^ (krow & 7)) << 4));
            MMA_F16(O[2 * jj], a, v0, v1);
            MMA_F16(O[2 * jj + 1], a, v2, v3);
        }
    }

    __half* ob = att + grow0 * CH + h * HDD;
#pragma unroll
    for (int j = 0; j < 8; j++) {
        int c = 8 * j + 2 * tg;
        *(__half2*)(ob + (size_t)r_lo * CH + c) =
            __floats2half2_rn(O[j][0] * invlo, O[j][1] * invlo);
        *(__half2*)(ob + (size_t)r_hi * CH + c) =
            __floats2half2_rn(O[j][2] * invhi, O[j][3] * invhi);
    }
}

// ---------------- launch ----------------------------------------------------
extern "C" void kernel_launch(void* const* d_in, const int* in_sizes, int n_in,
                              void* d_out, int out_size)
{
    const float* x      = (const float*)d_in[0];
    const float* mask   = (const float*)d_in[1];
    const float* w_qkv  = (const float*)d_in[2];
    const float* b_qkv  = (const float*)d_in[3];
    const float* w_proj = (const float*)d_in[4];
    const float* b_proj = (const float*)d_in[5];
    const float* btab   = (const float*)d_in[6];
    float* out = (float*)d_out;

    __half *qkvh, *xh, *ath, *wqh, *wph;
    cudaGetSymbolAddress((void**)&qkvh, g_qkvh);
    cudaGetSymbolAddress((void**)&xh, g_xh);
    cudaGetSymbolAddress((void**)&ath, g_ath);
    cudaGetSymbolAddress((void**)&wqh, g_wqh);
    cudaGetSymbolAddress((void**)&wph, g_wph);

    cudaFuncSetAttribute(gemm_mma<__half>, cudaFuncAttributeMaxDynamicSharedMemorySize,
                         GEMM_SMEM);
    cudaFuncSetAttribute(gemm_mma<float>, cudaFuncAttributeMaxDynamicSharedMemorySize,
                         GEMM_SMEM);
    cudaFuncSetAttribute(attn_mma, cudaFuncAttributeMaxDynamicSharedMemorySize,
                         ATTN_SMEM);

    // prepass
    conv_h<<<(MROWS * KC) / (256 * 4), 256>>>(x, xh);
    transpose_h<<<dim3(N1 / 32, KC / 32), dim3(32, 8)>>>(w_qkv, wqh, KC, N1);
    transpose_h<<<dim3(CH / 32, KC / 32), dim3(32, 8)>>>(w_proj, wph, KC, CH);

    // GEMM1: qkv(fp16) = x @ w_qkv + b_qkv
    gemm_mma<__half><<<dim3(N1 / 128, MROWS / 128), 128, GEMM_SMEM>>>(
        xh, wqh, b_qkv, qkvh, N1);
    // attention (fp16 out)
    attn_mma<<<dim3(NHH, BWT), 256, ATTN_SMEM>>>(qkvh, mask, btab, ath);
    // GEMM2: out(fp32) = att @ w_proj + b_proj
    gemm_mma<float><<<dim3(CH / 128, MROWS / 128), 128, GEMM_SMEM>>>(
        ath, wph, b_proj, out, CH);
}

// round 11
// speedup vs baseline: 7.2580x; 1.0032x over previous
#include <cuda_runtime.h>
#include <cuda_fp16.h>
#include <cstdint>
#include <cstddef>

// Problem constants
#define BWT   1024
#define WIN_  128
#define CH    512
#define NHH   8
#define HDD   64
#define MROWS (BWT * WIN_)   // 131072
#define N1    (3 * CH)       // 1536
#define KC    512

// ---------------- scratch (device globals) ----------------------------------
__device__ __half g_qkvh[(size_t)MROWS * N1];  // fp16 qkv (GEMM1 out, attn in)
__device__ __half g_xh[(size_t)MROWS * KC];    // fp16(x)
__device__ __half g_ath[(size_t)MROWS * CH];   // fp16 attention out (GEMM2 in)
__device__ __half g_wqh[(size_t)N1 * KC];      // fp16(w_qkv^T)  [N1][K]
__device__ __half g_wph[(size_t)CH * KC];      // fp16(w_proj^T) [CH][K]

// ---------------- helpers ----------------------------------------------------
__device__ __forceinline__ uint32_t smem_u32(const void* p) {
    uint32_t a;
    asm("{ .reg .u64 t; cvta.to.shared.u64 t, %1; cvt.u32.u64 %0, t; }" : "=r"(a) : "l"(p));
    return a;
}

#define CP_ASYNC16(dst, src) \
    asm volatile("cp.async.cg.shared.global [%0], [%1], 16;" :: "r"(dst), "l"(src) : "memory")
#define CP_COMMIT()  asm volatile("cp.async.commit_group;" ::: "memory")
#define CP_WAIT1()   asm volatile("cp.async.wait_group 1;" ::: "memory")
#define CP_WAIT0()   asm volatile("cp.async.wait_group 0;" ::: "memory")

#define LDM4(r0, r1, r2, r3, addr) \
    asm volatile("ldmatrix.sync.aligned.m8n8.x4.shared.b16 {%0,%1,%2,%3}, [%4];" \
        : "=r"(r0), "=r"(r1), "=r"(r2), "=r"(r3) : "r"(addr))
#define LDM4T(r0, r1, r2, r3, addr) \
    asm volatile("ldmatrix.sync.aligned.m8n8.x4.trans.shared.b16 {%0,%1,%2,%3}, [%4];" \
        : "=r"(r0), "=r"(r1), "=r"(r2), "=r"(r3) : "r"(addr))

#define MMA_F16(d, a, b0, b1) \
    asm volatile("mma.sync.aligned.m16n8k16.row.col.f32.f16.f16.f32 " \
        "{%0,%1,%2,%3}, {%4,%5,%6,%7}, {%8,%9}, {%0,%1,%2,%3};" \
        : "+f"((d)[0]), "+f"((d)[1]), "+f"((d)[2]), "+f"((d)[3]) \
        : "r"((a)[0]), "r"((a)[1]), "r"((a)[2]), "r"((a)[3]), "r"(b0), "r"(b1))

__device__ __forceinline__ uint32_t h2u(float a, float b) {
    __half2 h = __floats2half2_rn(a, b);
    return *(uint32_t*)&h;
}
__device__ __forceinline__ void store2(float* p, float a, float b) {
    *(float2*)p = make_float2(a, b);
}
__device__ __forceinline__ void store2(__half* p, float a, float b) {
    *(__half2*)p = __floats2half2_rn(a, b);
}

// ---------------- prepass: x -> fp16 ------------------------------------------
__global__ void conv_h(const float* __restrict__ in, __half* __restrict__ o) {
    size_t i = ((size_t)blockIdx.x * blockDim.x + threadIdx.x) * 4;
    float4 v = *(const float4*)(in + i);
    __half h[4] = {__float2half_rn(v.x), __float2half_rn(v.y),
                   __float2half_rn(v.z), __float2half_rn(v.w)};
    *(uint2*)(o + i) = *(uint2*)h;
}

// ---------------- prepass: transpose weights -> fp16 [N][K] -------------------
__global__ void transpose_h(const float* __restrict__ W,
                            __half* __restrict__ Th, int K, int N) {
    __shared__ float t[32][33];
    int kb = blockIdx.y * 32, nb = blockIdx.x * 32;
    for (int i = threadIdx.y; i < 32; i += 8)
        t[i][threadIdx.x] = W[(size_t)(kb + i) * N + nb + threadIdx.x];
    __syncthreads();
    for (int i = threadIdx.y; i < 32; i += 8)
        Th[(size_t)(nb + i) * K + kb + threadIdx.x] = __float2half_rn(t[threadIdx.x][i]);
}

// ---------------- fp16 HMMA GEMM: C[M,N] = A @ Bt^T + bias -------------------
// CTA 128x128, BK=64, 128 threads (4 warps, 2x2 grid, warp tile 64x64).
// 3-stage cp.async pipeline (32KB/stage), 2 CTAs/SM. cp.async issue split
// around slab-0 MMAs to avoid a 16-op LSU issue burst blocking MMA issue.
#define STAGE_B 32768
#define GEMM_SMEM (3 * STAGE_B)

template <typename OutT>
__global__ __launch_bounds__(128, 2)
void gemm_mma(const __half* __restrict__ Ah, const __half* __restrict__ Bh,
              const float* __restrict__ bias, OutT* __restrict__ C, int N)
{
    extern __shared__ char smem[];
    const uint32_t sbase = smem_u32(smem);
    const int tid = threadIdx.x;
    const int lane = tid & 31, wid = tid >> 5;
    const int wm = wid & 1, wn = wid >> 1;          // 2 x 2 warp grid
    const size_t m0 = (size_t)blockIdx.y * 128;
    const size_t n0 = (size_t)blockIdx.x * 128;

    // loader: per stage 256 rows x 128B; thread handles rows r0+16t, chunk c.
    const int r0 = tid >> 3, c = tid & 7;
    const __half* srcA = Ah + (m0 + r0) * KC + c * 8;
    const __half* srcB = Bh + (n0 + r0) * KC + c * 8;
    const uint32_t dstA = sbase + r0 * 128 + (uint32_t)((c ^ (r0 & 7)) << 4);
    const uint32_t dstB = dstA + 16384;

#define LOAD_PART(buf, k0, T0, T1) do {                                  \
        uint32_t so = (uint32_t)(buf) * STAGE_B;                         \
        _Pragma("unroll")                                                \
        for (int t = (T0); t < (T1); t++) {                              \
            CP_ASYNC16(dstA + so + t * 2048, srcA + (k0) + t * 16 * KC); \
            CP_ASYNC16(dstB + so + t * 2048, srcB + (k0) + t * 16 * KC); \
        }                                                                \
    } while (0)

    // fragment loads for one k16 slab
    const int arow = wm * 64 + (lane & 15);
    const int brow_ = wn * 64 + (lane & 7) + ((lane >> 4) << 3);
#define LD_AFRAG(fa, stb, slab) do {                                       \
        _Pragma("unroll")                                                  \
        for (int mi = 0; mi < 4; mi++) {                                   \
            int row = arow + mi * 16;                                      \
            int kc = ((slab) << 1) + (lane >> 4);                          \
            LDM4((fa)[mi][0], (fa)[mi][1], (fa)[mi][2], (fa)[mi][3],       \
                 (stb) + row * 128 + ((kc ^ (row & 7)) << 4));             \
        }                                                                  \
    } while (0)
#define LD_BFRAG(bh, stb, slab) do {                                       \
        _Pragma("unroll")                                                  \
        for (int nj = 0; nj < 4; nj++) {                                   \
            int row = brow_ + nj * 16;                                     \
            int kc = ((slab) << 1) + ((lane >> 3) & 1);                    \
            LDM4((bh)[nj][0], (bh)[nj][1], (bh)[nj][2], (bh)[nj][3],       \
                 (stb) + 16384 + row * 128 + ((kc ^ (row & 7)) << 4));     \
        }                                                                  \
    } while (0)

    float D[4][8][4];
#pragma unroll
    for (int i = 0; i < 4; i++)
#pragma unroll
        for (int j = 0; j < 8; j++)
#pragma unroll
            for (int q = 0; q < 4; q++) D[i][j][q] = 0.0f;

    LOAD_PART(0, 0, 0, 8);  CP_COMMIT();
    LOAD_PART(1, 64, 0, 8); CP_COMMIT();

    uint32_t fa[2][4][4], fb[2][4][4];

    const int NSTAGE = KC / 64;   // 8
#pragma unroll 1
    for (int s = 0; s < NSTAGE; s++) {
        if (s + 1 < NSTAGE) { CP_WAIT1(); } else { CP_WAIT0(); }
        __syncthreads();

        int bufc = s; bufc -= (bufc >= 3) ? 3 : 0; bufc -= (bufc >= 3) ? 3 : 0;
        bufc -= (bufc >= 3) ? 3 : 0;
        const uint32_t stb = sbase + (uint32_t)bufc * STAGE_B;

        const bool havenext = (s + 2 < NSTAGE);
        int nb = s + 2; nb -= (nb >= 3) ? 3 : 0; nb -= (nb >= 3) ? 3 : 0;
        const int nk0 = (s + 2) * 64;

        // preload slab 0 fragments, then half the next-stage gmem loads
        LD_BFRAG(fb[0], stb, 0);
        LD_AFRAG(fa[0], stb, 0);
        if (havenext) LOAD_PART(nb, nk0, 0, 4);

#pragma unroll
        for (int slab = 0; slab < 4; slab++) {
            const int cur = slab & 1, nxt = cur ^ 1;
            if (slab < 3) {
                LD_BFRAG(fb[nxt], stb, slab + 1);
                LD_AFRAG(fa[nxt], stb, slab + 1);
            }
#pragma unroll
            for (int mi = 0; mi < 4; mi++)
#pragma unroll
                for (int n8 = 0; n8 < 8; n8++) {
                    const int nj = n8 >> 1, hb = (n8 & 1) * 2;
                    MMA_F16(D[mi][n8], fa[cur][mi], fb[cur][nj][hb], fb[cur][nj][hb + 1]);
                }
            if (slab == 0 && havenext) { LOAD_PART(nb, nk0, 4, 8); CP_COMMIT(); }
        }
    }

    // epilogue
    const int gr = lane >> 2, tg = lane & 3;
#pragma unroll
    for (int mi = 0; mi < 4; mi++) {
        size_t rowa = m0 + wm * 64 + mi * 16 + gr;
#pragma unroll
        for (int n8 = 0; n8 < 8; n8++) {
            int col = (int)n0 + wn * 64 + n8 * 8 + tg * 2;
            float b0v = bias[col], b1v = bias[col + 1];
            store2(C + rowa * N + col, D[mi][n8][0] + b0v, D[mi][n8][1] + b1v);
            store2(C + (rowa + 8) * N + col, D[mi][n8][2] + b0v, D[mi][n8][3] + b1v);
        }
    }
}

// ---------------- HMMA window attention: one CTA per (head, window) ----------
// 8 warps x 16 q-rows. Exp'd scores packed to fp16 immediately (frees the
// fp32 D array) -> <=128 regs -> 2 CTAs/SM for latency overlap.
#define ATTN_SMEM (3 * 16384 + 1024)

__global__ __launch_bounds__(256, 2)
void attn_mma(const __half* __restrict__ qkv, const float* __restrict__ mask,
              const float* __restrict__ btab, __half* __restrict__ att)
{
    const int h = blockIdx.x;
    const int b = blockIdx.y;
    const int tid = threadIdx.x;
    const int lane = tid & 31, w = tid >> 5;
    const int gr = lane >> 2, tg = lane & 3;

    extern __shared__ char smc[];
    const uint32_t Qb = smem_u32(smc);
    const uint32_t Kb = Qb + 16384;
    const uint32_t Vb = Qb + 32768;
    float* bs = (float*)(smc + 49152);

    const size_t grow0 = (size_t)b * WIN_;
#pragma unroll
    for (int i = 0; i < 4; i++) {
        int g = tid + 256 * i;
        int r = g >> 3, c = g & 7;
        const __half* src = qkv + (grow0 + r) * N1 + h * HDD + c * 8;
        uint32_t doff = r * 128 + (uint32_t)((c ^ (r & 7)) << 4);
        CP_ASYNC16(Qb + doff, src);
        CP_ASYNC16(Kb + doff, src + CH);
        CP_ASYNC16(Vb + doff, src + 2 * CH);
    }
    CP_COMMIT();
    if (tid < 255) bs[tid] = btab[tid * NHH + h];
    CP_WAIT0();
    __syncthreads();

    const int m0 = w * 16;
    const int r_lo = m0 + gr, r_hi = m0 + gr + 8;

    // ---- S = Q K^T ----
    float D[16][4];
#pragma unroll
    for (int j = 0; j < 16; j++)
#pragma unroll
        for (int c2 = 0; c2 < 4; c2++) D[j][c2] = 0.0f;

#pragma unroll
    for (int s = 0; s < 4; s++) {
        uint32_t a[4];
        {
            int row = m0 + (lane & 15);
            int kc = (s << 1) + (lane >> 4);
            LDM4(a[0], a[1], a[2], a[3], Qb + row * 128 + ((kc ^ (row & 7)) << 4));
        }
#pragma unroll
        for (int jj = 0; jj < 8; jj++) {
            uint32_t v0, v1, v2, v3;
            int grp = lane >> 3;
            int nrow = jj * 16 + ((grp >> 1) & 1) * 8 + (lane & 7);
            int kc = (s << 1) + (grp & 1);
            LDM4(v0, v1, v2, v3, Kb + nrow * 128 + ((kc ^ (nrow & 7)) << 4));
            MMA_F16(D[2 * jj], a, v0, v1);
            MMA_F16(D[2 * jj + 1], a, v2, v3);
        }
    }

    // ---- scale + rel-pos bias + window mask ----
    const float* mrow = mask + (size_t)(b & 63) * (WIN_ * WIN_);
#pragma unroll
    for (int j = 0; j < 16; j++) {
        int c = 8 * j + 2 * tg;
        float2 mlo2 = *(const float2*)(mrow + r_lo * 128 + c);
        float2 mhi2 = *(const float2*)(mrow + r_hi * 128 + c);
        D[j][0] = D[j][0] * 0.125f + bs[c - r_lo + 127] + mlo2.x;
        D[j][1] = D[j][1] * 0.125f + bs[c + 1 - r_lo + 127] + mlo2.y;
        D[j][2] = D[j][2] * 0.125f + bs[c - r_hi + 127] + mhi2.x;
        D[j][3] = D[j][3] * 0.125f + bs[c + 1 - r_hi + 127] + mhi2.y;
    }

    // ---- in-register softmax; pack exp to fp16 immediately ----
    float mlo = -1e30f, mhi = -1e30f;
#pragma unroll
    for (int j = 0; j < 16; j++) {
        mlo = fmaxf(mlo, fmaxf(D[j][0], D[j][1]));
        mhi = fmaxf(mhi, fmaxf(D[j][2], D[j][3]));
    }
    mlo = fmaxf(mlo, __shfl_xor_sync(0xffffffffu, mlo, 1));
    mlo = fmaxf(mlo, __shfl_xor_sync(0xffffffffu, mlo, 2));
    mhi = fmaxf(mhi, __shfl_xor_sync(0xffffffffu, mhi, 1));
    mhi = fmaxf(mhi, __shfl_xor_sync(0xffffffffu, mhi, 2));

    uint32_t Pk[16][2];
    float slo = 0.0f, shi = 0.0f;
#pragma unroll
    for (int j = 0; j < 16; j++) {
        float e0 = __expf(D[j][0] - mlo);
        float e1 = __expf(D[j][1] - mlo);
        float e2 = __expf(D[j][2] - mhi);
        float e3 = __expf(D[j][3] - mhi);
        slo += e0 + e1;
        shi += e2 + e3;
        Pk[j][0] = h2u(e0, e1);
        Pk[j][1] = h2u(e2, e3);
    }
    slo += __shfl_xor_sync(0xffffffffu, slo, 1);
    slo += __shfl_xor_sync(0xffffffffu, slo, 2);
    shi += __shfl_xor_sync(0xffffffffu, shi, 1);
    shi += __shfl_xor_sync(0xffffffffu, shi, 2);
    const float invlo = 1.0f / slo, invhi = 1.0f / shi;

    // ---- O = P V ----
    float O[8][4];
#pragma unroll
    for (int j = 0; j < 8; j++)
#pragma unroll
        for (int c2 = 0; c2 < 4; c2++) O[j][c2] = 0.0f;

#pragma unroll
    for (int s = 0; s < 8; s++) {
        uint32_t a[4];
        a[0] = Pk[2 * s][0];
        a[1] = Pk[2 * s][1];
        a[2] = Pk[2 * s + 1][0];
        a[3] = Pk[2 * s + 1][1];
#pragma unroll
        for (int jj = 0; jj < 4; jj++) {
            uint32_t v0, v1, v2, v3;
            int grp = lane >> 3;
            int krow = 16 * s + (grp & 1) * 8 + (lane & 7);
            int nc = (jj << 1) + ((grp >> 1) & 1);
            LDM4T(v0, v1, v2, v3, Vb + krow * 128 + ((nc ^ (krow & 7)) << 4));
            MMA_F16(O[2 * jj], a, v0, v1);
            MMA_F16(O[2 * jj + 1], a, v2, v3);
        }
    }

    __half* ob = att + grow0 * CH + h * HDD;
#pragma unroll
    for (int j = 0; j < 8; j++) {
        int c = 8 * j + 2 * tg;
        *(__half2*)(ob + (size_t)r_lo * CH + c) =
            __floats2half2_rn(O[j][0] * invlo, O[j][1] * invlo);
        *(__half2*)(ob + (size_t)r_hi * CH + c) =
            __floats2half2_rn(O[j][2] * invhi, O[j][3] * invhi);
    }
}

// ---------------- launch ----------------------------------------------------
extern "C" void kernel_launch(void* const* d_in, const int* in_sizes, int n_in,
                              void* d_out, int out_size)
{
    const float* x      = (const float*)d_in[0];
    const float* mask   = (const float*)d_in[1];
    const float* w_qkv  = (const float*)d_in[2];
    const float* b_qkv  = (const float*)d_in[3];
    const float* w_proj = (const float*)d_in[4];
    const float* b_proj = (const float*)d_in[5];
    const float* btab   = (const float*)d_in[6];
    float* out = (float*)d_out;

    __half *qkvh, *xh, *ath, *wqh, *wph;
    cudaGetSymbolAddress((void**)&qkvh, g_qkvh);
    cudaGetSymbolAddress((void**)&xh, g_xh);
    cudaGetSymbolAddress((void**)&ath, g_ath);
    cudaGetSymbolAddress((void**)&wqh, g_wqh);
    cudaGetSymbolAddress((void**)&wph, g_wph);

    cudaFuncSetAttribute(gemm_mma<__half>, cudaFuncAttributeMaxDynamicSharedMemorySize,
                         GEMM_SMEM);
    cudaFuncSetAttribute(gemm_mma<float>, cudaFuncAttributeMaxDynamicSharedMemorySize,
                         GEMM_SMEM);
    cudaFuncSetAttribute(attn_mma, cudaFuncAttributeMaxDynamicSharedMemorySize,
                         ATTN_SMEM);

    // prepass
    conv_h<<<(MROWS * KC) / (256 * 4), 256>>>(x, xh);
    transpose_h<<<dim3(N1 / 32, KC / 32), dim3(32, 8)>>>(w_qkv, wqh, KC, N1);
    transpose_h<<<dim3(CH / 32, KC / 32), dim3(32, 8)>>>(w_proj, wph, KC, CH);

    // GEMM1: qkv(fp16) = x @ w_qkv + b_qkv
    gemm_mma<__half><<<dim3(N1 / 128, MROWS / 128), 128, GEMM_SMEM>>>(
        xh, wqh, b_qkv, qkvh, N1);
    // attention (fp16 out)
    attn_mma<<<dim3(NHH, BWT), 256, ATTN_SMEM>>>(qkvh, mask, btab, ath);
    // GEMM2: out(fp32) = att @ w_proj + b_proj
    gemm_mma<float><<<dim3(CH / 128, MROWS / 128), 128, GEMM_SMEM>>>(
        ath, wph, b_proj, out, CH);
}